// round 2
// baseline (speedup 1.0000x reference)
#include <cuda_runtime.h>
#include <cuda_bf16.h>
#include <math.h>

// Problem constants
#define BB 2
#define SS 2048
#define HID 2048
#define HH 16
#define DD 128
#define RANK 512
#define BS (BB*SS)          // 4096
#define KVA_N (RANK + DD)   // 640
#define MSCALE 1.2772588722239782f
#define ATT_SCALE 0.08838834764831845f  // 1/sqrt(128)

// ---------------- scratch (device globals; no allocation allowed) -------------
__device__ float g_q[BS * (HH*DD)];        // q pre-rope  [BS, 2048]
__device__ float g_kva[BS * KVA_N];        // kv_a        [BS, 640]
__device__ float g_ckv[BS * RANK];         // rms-normed  [BS, 512]
__device__ float g_kvb[BS * (HH*2*DD)];    // kv          [BS, 4096]
__device__ float g_qr[BB*HH*SS*DD];        // q roped     [B,H,S,D]
__device__ float g_k [BB*HH*SS*DD];        // k           [B,H,S,D]
__device__ float g_v [BB*HH*SS*DD];        // v           [B,H,S,D]
__device__ float g_attn[BS * (HH*DD)];     // attn out    [BS, 2048]

// ---------------- generic tiled SGEMM: C[M,N] = A[M,K] @ B[K,N] ---------------
// BM=128, BN=128, BK=16, TM=TN=8, 256 threads. All dims divisible.
__global__ __launch_bounds__(256) void sgemm(const float* __restrict__ A,
                                             const float* __restrict__ B,
                                             float* __restrict__ C,
                                             int M, int N, int K)
{
    __shared__ float As[16][132];   // [k][m], padded
    __shared__ float Bs[16][132];   // [k][n], padded

    const int bx = blockIdx.x;      // N tile
    const int by = blockIdx.y;      // M tile
    const int tid = threadIdx.x;
    const int tx = tid & 15;        // 16 threads across N
    const int ty = tid >> 4;        // 16 threads across M

    const int arow  = tid >> 2;         // 0..63 (and +64)
    const int acol4 = (tid & 3) << 2;   // 0,4,8,12
    const int brow  = tid >> 5;         // 0..7 (and +8)
    const int bcol4 = (tid & 31) << 2;  // 0..124

    const float* Ab = A + (size_t)(by*128) * K;
    const float* Bb = B + bx*128;

    float acc[8][8];
#pragma unroll
    for (int i = 0; i < 8; i++)
#pragma unroll
        for (int j = 0; j < 8; j++) acc[i][j] = 0.f;

    for (int k0 = 0; k0 < K; k0 += 16) {
#pragma unroll
        for (int r = 0; r < 2; r++) {
            float4 a = *(const float4*)(Ab + (size_t)(arow + r*64)*K + k0 + acol4);
            As[acol4+0][arow + r*64] = a.x;
            As[acol4+1][arow + r*64] = a.y;
            As[acol4+2][arow + r*64] = a.z;
            As[acol4+3][arow + r*64] = a.w;
        }
#pragma unroll
        for (int r = 0; r < 2; r++) {
            float4 b = *(const float4*)(Bb + (size_t)(k0 + brow + r*8)*N + bcol4);
            *(float4*)&Bs[brow + r*8][bcol4] = b;
        }
        __syncthreads();
#pragma unroll
        for (int k = 0; k < 16; k++) {
            float ar[8], br[8];
#pragma unroll
            for (int i = 0; i < 8; i++) ar[i] = As[k][ty*8 + i];
#pragma unroll
            for (int j = 0; j < 8; j++) br[j] = Bs[k][tx*8 + j];
#pragma unroll
            for (int i = 0; i < 8; i++)
#pragma unroll
                for (int j = 0; j < 8; j++) acc[i][j] = fmaf(ar[i], br[j], acc[i][j]);
        }
        __syncthreads();
    }

    float* Cb = C + (size_t)(by*128 + ty*8) * N + bx*128 + tx*8;
#pragma unroll
    for (int i = 0; i < 8; i++) {
        float4 v0 = make_float4(acc[i][0], acc[i][1], acc[i][2], acc[i][3]);
        float4 v1 = make_float4(acc[i][4], acc[i][5], acc[i][6], acc[i][7]);
        *(float4*)(Cb + (size_t)i*N)     = v0;
        *(float4*)(Cb + (size_t)i*N + 4) = v1;
    }
}

// ---------------- RMSNorm over first 512 cols of kv_a -------------------------
__global__ __launch_bounds__(256) void rmsnorm_k(const float* __restrict__ kva,
                                                 const float* __restrict__ w,
                                                 float* __restrict__ out)
{
    const int row = blockIdx.x;
    const float* x = kva + (size_t)row * KVA_N;
    float s = 0.f;
    for (int i = threadIdx.x; i < RANK; i += 256) { float v = x[i]; s = fmaf(v, v, s); }
#pragma unroll
    for (int o = 16; o; o >>= 1) s += __shfl_xor_sync(0xffffffffu, s, o);
    __shared__ float red[8];
    __shared__ float inv_s;
    if ((threadIdx.x & 31) == 0) red[threadIdx.x >> 5] = s;
    __syncthreads();
    if (threadIdx.x == 0) {
        float t = 0.f;
#pragma unroll
        for (int i = 0; i < 8; i++) t += red[i];
        inv_s = rsqrtf(t * (1.f/512.f) + 1e-6f);
    }
    __syncthreads();
    const float inv = inv_s;
    for (int i = threadIdx.x; i < RANK; i += 256)
        out[(size_t)row * RANK + i] = w[i] * (x[i] * inv);
}

// ---------------- YaRN RoPE + k/v assembly into [B,H,S,D] ---------------------
__global__ __launch_bounds__(256) void rope_combine(const float* __restrict__ qpre,
                                                    const float* __restrict__ kva,
                                                    const float* __restrict__ kvb,
                                                    const int*   __restrict__ pos_ids,
                                                    float* __restrict__ qO,
                                                    float* __restrict__ kO,
                                                    float* __restrict__ vO)
{
    const int row = blockIdx.x;        // b*S + s
    const int b = row >> 11;
    const int s = row & 2047;
    const int tid = threadIdx.x;

    __shared__ float cs[128], sn[128], krot[128];
    const float pos = (float)pos_ids[row];

    if (tid < 128) {
        const int j = tid & 63;
        const float fj = (float)j;
        // inv_freq (YaRN): extrap = base^(-j/64); low=18, high=35 (precomputed)
        const float extrap = expf(-fj * 0.015625f * 13.122363377404328f);
        float smooth = (fj - 18.f) * (1.f / 17.f);
        smooth = fminf(fmaxf(smooth, 0.f), 1.f);
        const float invf = extrap * ((1.f - smooth) * 0.0625f + smooth);
        const float fr = pos * invf;
        cs[tid] = cosf(fr) * MSCALE;
        sn[tid] = sinf(fr) * MSCALE;
        krot[tid] = kva[(size_t)row * KVA_N + RANK + tid];
    }
    __syncthreads();
    float kv_ = 0.f;
    if (tid < 128) {
        const int d = tid;
        const float x = krot[d];
        const float pr = (d < 64) ? -krot[d + 64] : krot[d - 64];
        kv_ = fmaf(x, cs[d], pr * sn[d]);
    }
    __syncthreads();
    if (tid < 128) krot[tid] = kv_;
    __syncthreads();

    for (int e = tid; e < HH*DD; e += 256) {
        const int h = e >> 7, d = e & 127;
        const float x  = qpre[(size_t)row * (HH*DD) + e];
        const float pr = qpre[(size_t)row * (HH*DD) + h*128 + ((d < 64) ? d + 64 : d - 64)];
        const float qv = (d < 64) ? fmaf(x, cs[d], -pr * sn[d])
                                  : fmaf(x, cs[d],  pr * sn[d]);
        const size_t oidx = (((size_t)(b*HH + h)) * SS + s) * DD + d;
        qO[oidx] = qv;
        kO[oidx] = kvb[(size_t)row * (HH*2*DD) + h*256 + d] + krot[d];
        vO[oidx] = kvb[(size_t)row * (HH*2*DD) + h*256 + 128 + d];
    }
}

// ---------------- flash attention (fp32, causal) ------------------------------
// grid (S/64, B*H), 128 threads. BM=BN=64, D=128.
#define FLASH_SMEM_FLOATS (128*65*2 + 64*128 + 64*68 + 64*3)
#define FLASH_SMEM_BYTES  (FLASH_SMEM_FLOATS * 4)

__global__ __launch_bounds__(128) void flash_attn(const float* __restrict__ Q,
                                                  const float* __restrict__ Kg,
                                                  const float* __restrict__ Vg,
                                                  float* __restrict__ O)
{
    const int mt = blockIdx.x;   // query tile (0..31)
    const int bh = blockIdx.y;   // b*H + h    (0..31)
    const int b = bh >> 4, h = bh & 15;
    const int tid = threadIdx.x;
    const int w = tid >> 5, lane = tid & 31;
    const int lr = lane >> 3, lc = lane & 7;
    const int i0 = w*16 + lr*4;       // 4 query rows per thread
    const int j0 = lc*8;              // 8 key cols per thread (scores)

    extern __shared__ float sm[];
    float* QsT = sm;                    // [128][65]
    float* KsT = QsT + 128*65;          // [128][65]
    float* Vs  = KsT + 128*65;          // [64][128]
    float* Ps  = Vs  + 64*128;          // [64][68]
    float* m_s    = Ps + 64*68;         // [64]
    float* se_s   = m_s + 64;           // [64]
    float* corr_s = se_s + 64;          // [64]

    const float* Qb = Q + ((size_t)bh * SS + mt*64) * DD;
    for (int t = tid; t < 64*32; t += 128) {
        const int i = t >> 5;
        const int c4 = (t & 31) << 2;
        float4 v = *(const float4*)(Qb + (size_t)i*DD + c4);
        QsT[(c4+0)*65 + i] = v.x;
        QsT[(c4+1)*65 + i] = v.y;
        QsT[(c4+2)*65 + i] = v.z;
        QsT[(c4+3)*65 + i] = v.w;
    }
    if (tid < 64) { m_s[tid] = -1e30f; se_s[tid] = 0.f; }

    float acc[4][16];
#pragma unroll
    for (int a = 0; a < 4; a++)
#pragma unroll
        for (int c = 0; c < 16; c++) acc[a][c] = 0.f;

    for (int nt = 0; nt <= mt; nt++) {
        __syncthreads();   // protects Ps/K/V reuse + first-iter Q/m_s visibility
        const float* Kb = Kg + ((size_t)bh * SS + nt*64) * DD;
        const float* Vb = Vg + ((size_t)bh * SS + nt*64) * DD;
        for (int t = tid; t < 64*32; t += 128) {
            const int i = t >> 5;
            const int c4 = (t & 31) << 2;
            float4 v = *(const float4*)(Kb + (size_t)i*DD + c4);
            KsT[(c4+0)*65 + i] = v.x;
            KsT[(c4+1)*65 + i] = v.y;
            KsT[(c4+2)*65 + i] = v.z;
            KsT[(c4+3)*65 + i] = v.w;
            float4 u = *(const float4*)(Vb + (size_t)i*DD + c4);
            *(float4*)(Vs + i*128 + c4) = u;
        }
        __syncthreads();

        // scores: s[a][c] = sum_k Q[i0+a][k] * K[j0+c][k]
        float s[4][8];
#pragma unroll
        for (int a = 0; a < 4; a++)
#pragma unroll
            for (int c = 0; c < 8; c++) s[a][c] = 0.f;
        for (int k = 0; k < 128; k++) {
            float qr_[4], kr_[8];
#pragma unroll
            for (int a = 0; a < 4; a++) qr_[a] = QsT[k*65 + i0 + a];
#pragma unroll
            for (int c = 0; c < 8; c++) kr_[c] = KsT[k*65 + j0 + c];
#pragma unroll
            for (int a = 0; a < 4; a++)
#pragma unroll
                for (int c = 0; c < 8; c++) s[a][c] = fmaf(qr_[a], kr_[c], s[a][c]);
        }
        const bool diag = (nt == mt);
#pragma unroll
        for (int a = 0; a < 4; a++) {
            const int gi = i0 + a;
#pragma unroll
            for (int c = 0; c < 8; c++) {
                const int gj = j0 + c;
                float v = s[a][c] * ATT_SCALE;
                if (diag && gj > gi) v = -1e30f;
                Ps[gi*68 + gj] = v;
            }
        }
        __syncthreads();

        // per-row online-softmax stats: 2 threads per row, 32 cols each,
        // combined via shfl (lane pairs r and r+64 differ in bit 6 -> use
        // thread mapping: row = tid & 63, half = tid >> 6).
        {
            const int r    = tid & 63;
            const int half = tid >> 6;          // 0 or 1
            float* prow = Ps + r*68 + half*32;
            float rmax = -1e30f;
#pragma unroll 8
            for (int j = 0; j < 32; j++) rmax = fmaxf(rmax, prow[j]);
            // combine halves: partner thread is tid ^ 64 -> different warp, so
            // go through smem (reuse corr_s as scratch for half-0 first).
            __shared__ float hmax[128], hsum[128];
            hmax[tid] = rmax;
            __syncthreads();
            const float mold = m_s[r];
            const float rowmax = fmaxf(fmaxf(hmax[r], hmax[r + 64]), mold);
            float sum = 0.f;
#pragma unroll 8
            for (int j = 0; j < 32; j++) {
                const float p = expf(prow[j] - rowmax);
                prow[j] = p;
                sum += p;
            }
            hsum[tid] = sum;
            __syncthreads();
            if (tid < 64) {
                const float corr = expf(mold - rowmax);
                se_s[r] = se_s[r] * corr + hsum[r] + hsum[r + 64];
                m_s[r] = rowmax;
                corr_s[r] = corr;
            }
        }
        __syncthreads();

        // rescale + PV: thread owns cols d = lc*4 + q*32 + dd  (conflict-free V reads)
        float cr[4];
#pragma unroll
        for (int a = 0; a < 4; a++) cr[a] = corr_s[i0 + a];
#pragma unroll
        for (int a = 0; a < 4; a++)
#pragma unroll
            for (int c = 0; c < 16; c++) acc[a][c] *= cr[a];

        for (int j = 0; j < 64; j++) {
            float p[4];
#pragma unroll
            for (int a = 0; a < 4; a++) p[a] = Ps[(i0 + a)*68 + j];
#pragma unroll
            for (int q = 0; q < 4; q++) {
                const float4 vv = *(const float4*)(Vs + j*128 + lc*4 + q*32);
#pragma unroll
                for (int a = 0; a < 4; a++) {
                    acc[a][q*4+0] = fmaf(p[a], vv.x, acc[a][q*4+0]);
                    acc[a][q*4+1] = fmaf(p[a], vv.y, acc[a][q*4+1]);
                    acc[a][q*4+2] = fmaf(p[a], vv.z, acc[a][q*4+2]);
                    acc[a][q*4+3] = fmaf(p[a], vv.w, acc[a][q*4+3]);
                }
            }
        }
    }
    __syncthreads();

    // epilogue: write to g_attn as [b*S+s, h*128+d]
#pragma unroll
    for (int a = 0; a < 4; a++) {
        const int gi = i0 + a;
        const float inv = 1.f / (se_s[gi] + 1e-5f);
        const int row = b*SS + mt*64 + gi;
        float* Ob = O + (size_t)row * (HH*DD) + h*DD;
#pragma unroll
        for (int q = 0; q < 4; q++) {
            float4 o;
            o.x = acc[a][q*4+0] * inv;
            o.y = acc[a][q*4+1] * inv;
            o.z = acc[a][q*4+2] * inv;
            o.w = acc[a][q*4+3] * inv;
            *(float4*)(Ob + lc*4 + q*32) = o;
        }
    }
}

// ---------------- launch --------------------------------------------------------
extern "C" void kernel_launch(void* const* d_in, const int* in_sizes, int n_in,
                              void* d_out, int out_size)
{
    const float* hidden = (const float*)d_in[0];
    const int*   pos    = (const int*)  d_in[1];
    const float* w_q    = (const float*)d_in[2];
    const float* w_kv_a = (const float*)d_in[3];
    const float* w_kv_b = (const float*)d_in[4];
    const float* w_o    = (const float*)d_in[5];
    const float* kv_ln  = (const float*)d_in[6];
    float* out = (float*)d_out;

    float *q, *kva, *ckv, *kvb, *qr, *kk, *vv, *attn;
    cudaGetSymbolAddress((void**)&q,    g_q);
    cudaGetSymbolAddress((void**)&kva,  g_kva);
    cudaGetSymbolAddress((void**)&ckv,  g_ckv);
    cudaGetSymbolAddress((void**)&kvb,  g_kvb);
    cudaGetSymbolAddress((void**)&qr,   g_qr);
    cudaGetSymbolAddress((void**)&kk,   g_k);
    cudaGetSymbolAddress((void**)&vv,   g_v);
    cudaGetSymbolAddress((void**)&attn, g_attn);

    // 1. q = hidden @ w_q                   [4096,2048]x[2048,2048]
    sgemm<<<dim3(16, 32), 256>>>(hidden, w_q, q, BS, HH*DD, HID);
    // 2. kv_a = hidden @ w_kv_a             [4096,2048]x[2048,640]
    sgemm<<<dim3(5, 32), 256>>>(hidden, w_kv_a, kva, BS, KVA_N, HID);
    // 3. RMSNorm(c_kv)
    rmsnorm_k<<<BS, 256>>>(kva, kv_ln, ckv);
    // 4. kv = c_kv @ w_kv_b                 [4096,512]x[512,4096]
    sgemm<<<dim3(32, 32), 256>>>(ckv, w_kv_b, kvb, BS, HH*2*DD, RANK);
    // 5. RoPE + assemble q/k/v in [B,H,S,D]
    rope_combine<<<BS, 256>>>(q, kva, kvb, pos, qr, kk, vv);
    // 6. flash attention
    cudaFuncSetAttribute(flash_attn, cudaFuncAttributeMaxDynamicSharedMemorySize,
                         FLASH_SMEM_BYTES);
    flash_attn<<<dim3(SS/64, BB*HH), 128, FLASH_SMEM_BYTES>>>(qr, kk, vv, attn);
    // 7. out = attn @ w_o                   [4096,2048]x[2048,2048]
    sgemm<<<dim3(16, 32), 256>>>(attn, w_o, out, BS, HID, HH*DD);
}

// round 5
// speedup vs baseline: 1.3471x; 1.3471x over previous
#include <cuda_runtime.h>
#include <cuda_bf16.h>
#include <math.h>
#include <stdint.h>

// Problem constants
#define BB 2
#define SS 2048
#define HID 2048
#define HH 16
#define DD 128
#define RANK 512
#define BS (BB*SS)          // 4096
#define KVA_N (RANK + DD)   // 640
#define MSCALE 1.2772588722239782f
#define ATT_SCALE 0.08838834764831845f  // 1/sqrt(128)

// ---------------- scratch (device globals; no allocation allowed) -------------
__device__ float g_q[BS * (HH*DD)];
__device__ float g_kva[BS * KVA_N];
__device__ float g_ckv[BS * RANK];
__device__ float g_kvb[BS * (HH*2*DD)];
__device__ float g_qr[BB*HH*SS*DD];
__device__ float g_k [BB*HH*SS*DD];
__device__ float g_v [BB*HH*SS*DD];
__device__ float g_attn[BS * (HH*DD)];

// bf16 split operands (hi/lo). g_ah/g_al reused: hidden first, then attn.
__device__ __nv_bfloat16 g_ah[BS*HID],  g_al[BS*HID];            // A [4096,2048]
__device__ __nv_bfloat16 g_ckvh[BS*RANK], g_ckvl[BS*RANK];       // A [4096,512]
__device__ __nv_bfloat16 g_bqh[HID*HH*DD],   g_bql[HID*HH*DD];       // Bt[2048,2048]
__device__ __nv_bfloat16 g_bkah[KVA_N*HID],  g_bkal[KVA_N*HID];      // Bt[640,2048]
__device__ __nv_bfloat16 g_bkbh[HH*2*DD*RANK], g_bkbl[HH*2*DD*RANK]; // Bt[4096,512]
__device__ __nv_bfloat16 g_boh[HID*HH*DD],   g_bol[HID*HH*DD];       // Bt[2048,2048]

// =================== base-ISA helpers (compile for plain sm_103) ==============
__device__ __forceinline__ uint32_t smem_u32(const void* p) {
    uint32_t a;
    asm("{ .reg .u64 t; cvta.to.shared.u64 t, %1; cvt.u32.u64 %0, t; }"
        : "=r"(a) : "l"(p));
    return a;
}

#define CP_ASYNC16(dst, src) \
    asm volatile("cp.async.cg.shared.global [%0], [%1], 16;" :: "r"(dst), "l"(src))
#define CP_COMMIT() asm volatile("cp.async.commit_group;" ::: "memory")
#define CP_WAIT(n)  asm volatile("cp.async.wait_group %0;" :: "n"(n) : "memory")

__device__ __forceinline__ void ldm_x4(uint32_t a, uint32_t& r0, uint32_t& r1,
                                       uint32_t& r2, uint32_t& r3) {
    asm volatile("ldmatrix.sync.aligned.m8n8.x4.shared.b16 {%0,%1,%2,%3}, [%4];"
                 : "=r"(r0), "=r"(r1), "=r"(r2), "=r"(r3) : "r"(a));
}

__device__ __forceinline__ void mma_bf16(float* d, const uint32_t* a, const uint32_t* b) {
    asm volatile(
        "mma.sync.aligned.m16n8k16.row.col.f32.bf16.bf16.f32 "
        "{%0,%1,%2,%3}, {%4,%5,%6,%7}, {%8,%9}, {%0,%1,%2,%3};"
        : "+f"(d[0]), "+f"(d[1]), "+f"(d[2]), "+f"(d[3])
        : "r"(a[0]), "r"(a[1]), "r"(a[2]), "r"(a[3]), "r"(b[0]), "r"(b[1]));
}

// =================== split-bf16 tensor GEMM (mma.sync) ========================
// C[M,N] = (Ah+Al)[M,K] @ (Bh+Bl)^T,  Bt stored [N,K] row-major.
// CTA 128x128, 8 warps (2x4 -> 64x32 each), BK=32, cp.async double buffer.
// SMEM stage layout: op(Ah=0,Al=1,Bh=2,Bl=3) * 12288 + kb*6144 + row*48 + par*16
#define KB_BYTES    6144
#define OP_BYTES    12288
#define STAGE_BYTES 49152
#define HG_SMEM     (2*STAGE_BYTES)

__global__ __launch_bounds__(256) void hgemm(const __nv_bfloat16* __restrict__ Ah,
                                             const __nv_bfloat16* __restrict__ Al,
                                             const __nv_bfloat16* __restrict__ Bh,
                                             const __nv_bfloat16* __restrict__ Bl,
                                             float* __restrict__ C,
                                             int M, int N, int K)
{
    extern __shared__ char sm[];
    const uint32_t sb = smem_u32(sm);
    const int tid = threadIdx.x;
    const int wid = tid >> 5, lane = tid & 31;
    const int wm = wid >> 2, wn = wid & 3;          // warp 2x4 grid
    const int bx = blockIdx.x, by = blockIdx.y;

    const int r = lane & 7, grp = lane >> 3;
    const int a_row_off = ((grp & 1) << 3) + r;     // ldmatrix A lane->row
    const int a_par     = grp >> 1;
    const int b_row_off = ((grp >> 1) << 3) + r;    // ldmatrix B lane->row
    const int b_par     = grp & 1;

    const __nv_bfloat16* srcs[4] = {
        Ah + (size_t)by*128*K, Al + (size_t)by*128*K,
        Bh + (size_t)bx*128*K, Bl + (size_t)bx*128*K };

    float acc[4][4][4];
#pragma unroll
    for (int mt = 0; mt < 4; mt++)
#pragma unroll
        for (int nt = 0; nt < 4; nt++)
#pragma unroll
            for (int e = 0; e < 4; e++) acc[mt][nt][e] = 0.f;

    // async-load one K32 chunk into a stage
    auto issue = [&](int c, int st) {
#pragma unroll
        for (int i = 0; i < 8; i++) {
            const int op  = i >> 1;
            const int idx = tid + (i & 1)*256;       // 0..511
            const int row = idx >> 2, j = idx & 3;   // j: 16B chunk within 32-half row
            const __nv_bfloat16* s = srcs[op] + (size_t)row*K + c*32 + j*8;
            const uint32_t d = sb + st*STAGE_BYTES + op*OP_BYTES
                             + (j >> 1)*KB_BYTES + row*48 + (j & 1)*16;
            CP_ASYNC16(d, s);
        }
        CP_COMMIT();
    };

    const int NC = K >> 5;
    issue(0, 0);

    for (int c = 0; c < NC; c++) {
        const int st = c & 1;
        if (c + 1 < NC) { issue(c + 1, st ^ 1); CP_WAIT(1); }
        else            { CP_WAIT(0); }
        __syncthreads();

        const uint32_t sst = sb + st*STAGE_BYTES;
#pragma unroll
        for (int kb = 0; kb < 2; kb++) {
            uint32_t Bfh[4][2], Bfl[4][2];
#pragma unroll
            for (int np = 0; np < 2; np++) {
                const uint32_t ba = sst + 2*OP_BYTES + kb*KB_BYTES
                                  + (wn*32 + np*16 + b_row_off)*48 + b_par*16;
                ldm_x4(ba, Bfh[np*2][0], Bfh[np*2][1], Bfh[np*2+1][0], Bfh[np*2+1][1]);
                ldm_x4(ba + OP_BYTES,
                       Bfl[np*2][0], Bfl[np*2][1], Bfl[np*2+1][0], Bfl[np*2+1][1]);
            }
#pragma unroll
            for (int mt = 0; mt < 4; mt++) {
                const uint32_t aa = sst + kb*KB_BYTES
                                  + (wm*64 + mt*16 + a_row_off)*48 + a_par*16;
                uint32_t Afh[4], Afl[4];
                ldm_x4(aa, Afh[0], Afh[1], Afh[2], Afh[3]);
                ldm_x4(aa + OP_BYTES, Afl[0], Afl[1], Afl[2], Afl[3]);
#pragma unroll
                for (int nt = 0; nt < 4; nt++) {
                    mma_bf16(acc[mt][nt], Afh, Bfh[nt]);
                    mma_bf16(acc[mt][nt], Afh, Bfl[nt]);
                    mma_bf16(acc[mt][nt], Afl, Bfh[nt]);
                }
            }
        }
        __syncthreads();
    }

    // epilogue: thread t owns (m = base+t/4 [+8], n = base+2*(t%4))
    const int tq = lane >> 2, tr = lane & 3;
#pragma unroll
    for (int mt = 0; mt < 4; mt++) {
#pragma unroll
        for (int nt = 0; nt < 4; nt++) {
            const int m0 = by*128 + wm*64 + mt*16 + tq;
            const int n0 = bx*128 + wn*32 + nt*8 + tr*2;
            float2 v0 = make_float2(acc[mt][nt][0], acc[mt][nt][1]);
            float2 v1 = make_float2(acc[mt][nt][2], acc[mt][nt][3]);
            *(float2*)(C + (size_t)m0*N + n0)       = v0;
            *(float2*)(C + (size_t)(m0+8)*N + n0)   = v1;
        }
    }
}

// =================== bf16 split conversions ====================================
__global__ __launch_bounds__(256) void split_rows(const float* __restrict__ X,
                                                  __nv_bfloat16* __restrict__ H,
                                                  __nv_bfloat16* __restrict__ L,
                                                  int n4)
{
    const int i = blockIdx.x*256 + threadIdx.x;
    if (i >= n4) return;
    float4 v = ((const float4*)X)[i];
    __nv_bfloat16 h0 = __float2bfloat16(v.x), h1 = __float2bfloat16(v.y);
    __nv_bfloat16 h2 = __float2bfloat16(v.z), h3 = __float2bfloat16(v.w);
    __nv_bfloat16 l0 = __float2bfloat16(v.x - __bfloat162float(h0));
    __nv_bfloat16 l1 = __float2bfloat16(v.y - __bfloat162float(h1));
    __nv_bfloat16 l2 = __float2bfloat16(v.z - __bfloat162float(h2));
    __nv_bfloat16 l3 = __float2bfloat16(v.w - __bfloat162float(h3));
    ((__nv_bfloat162*)H)[i*2+0] = __nv_bfloat162(h0, h1);
    ((__nv_bfloat162*)H)[i*2+1] = __nv_bfloat162(h2, h3);
    ((__nv_bfloat162*)L)[i*2+0] = __nv_bfloat162(l0, l1);
    ((__nv_bfloat162*)L)[i*2+1] = __nv_bfloat162(l2, l3);
}

// transpose+split: X[Kd,Nd] fp32 -> H,L bf16 [Nd,Kd]
__global__ __launch_bounds__(256) void split_T(const float* __restrict__ X,
                                               __nv_bfloat16* __restrict__ H,
                                               __nv_bfloat16* __restrict__ L,
                                               int Kd, int Nd)
{
    __shared__ float t[32][33];
    const int tx = threadIdx.x & 31, ty = threadIdx.x >> 5;
    const int c0 = blockIdx.x*32, r0 = blockIdx.y*32;
#pragma unroll
    for (int i = 0; i < 4; i++)
        t[ty + i*8][tx] = X[(size_t)(r0 + ty + i*8)*Nd + c0 + tx];
    __syncthreads();
#pragma unroll
    for (int i = 0; i < 4; i++) {
        const float x = t[tx][ty + i*8];
        const __nv_bfloat16 h = __float2bfloat16(x);
        const __nv_bfloat16 l = __float2bfloat16(x - __bfloat162float(h));
        const size_t o = (size_t)(c0 + ty + i*8)*Kd + r0 + tx;
        H[o] = h; L[o] = l;
    }
}

// ---------------- RMSNorm over first 512 cols of kv_a -------------------------
__global__ __launch_bounds__(256) void rmsnorm_k(const float* __restrict__ kva,
                                                 const float* __restrict__ w,
                                                 float* __restrict__ out)
{
    const int row = blockIdx.x;
    const float* x = kva + (size_t)row * KVA_N;
    float s = 0.f;
    for (int i = threadIdx.x; i < RANK; i += 256) { float v = x[i]; s = fmaf(v, v, s); }
#pragma unroll
    for (int o = 16; o; o >>= 1) s += __shfl_xor_sync(0xffffffffu, s, o);
    __shared__ float red[8];
    __shared__ float inv_s;
    if ((threadIdx.x & 31) == 0) red[threadIdx.x >> 5] = s;
    __syncthreads();
    if (threadIdx.x == 0) {
        float t = 0.f;
#pragma unroll
        for (int i = 0; i < 8; i++) t += red[i];
        inv_s = rsqrtf(t * (1.f/512.f) + 1e-6f);
    }
    __syncthreads();
    const float inv = inv_s;
    for (int i = threadIdx.x; i < RANK; i += 256)
        out[(size_t)row * RANK + i] = w[i] * (x[i] * inv);
}

// ---------------- YaRN RoPE + k/v assembly into [B,H,S,D] ---------------------
__global__ __launch_bounds__(256) void rope_combine(const float* __restrict__ qpre,
                                                    const float* __restrict__ kva,
                                                    const float* __restrict__ kvb,
                                                    const int*   __restrict__ pos_ids,
                                                    float* __restrict__ qO,
                                                    float* __restrict__ kO,
                                                    float* __restrict__ vO)
{
    const int row = blockIdx.x;
    const int b = row >> 11;
    const int s = row & 2047;
    const int tid = threadIdx.x;

    __shared__ float cs[128], sn[128], krot[128];
    const float pos = (float)pos_ids[row];

    if (tid < 128) {
        const int j = tid & 63;
        const float fj = (float)j;
        const float extrap = expf(-fj * 0.015625f * 13.122363377404328f);
        float smooth = (fj - 18.f) * (1.f / 17.f);
        smooth = fminf(fmaxf(smooth, 0.f), 1.f);
        const float invf = extrap * ((1.f - smooth) * 0.0625f + smooth);
        const float fr = pos * invf;
        cs[tid] = cosf(fr) * MSCALE;
        sn[tid] = sinf(fr) * MSCALE;
        krot[tid] = kva[(size_t)row * KVA_N + RANK + tid];
    }
    __syncthreads();
    float kv_ = 0.f;
    if (tid < 128) {
        const int d = tid;
        const float x = krot[d];
        const float pr = (d < 64) ? -krot[d + 64] : krot[d - 64];
        kv_ = fmaf(x, cs[d], pr * sn[d]);
    }
    __syncthreads();
    if (tid < 128) krot[tid] = kv_;
    __syncthreads();

    for (int e = tid; e < HH*DD; e += 256) {
        const int h = e >> 7, d = e & 127;
        const float x  = qpre[(size_t)row * (HH*DD) + e];
        const float pr = qpre[(size_t)row * (HH*DD) + h*128 + ((d < 64) ? d + 64 : d - 64)];
        const float qv = (d < 64) ? fmaf(x, cs[d], -pr * sn[d])
                                  : fmaf(x, cs[d],  pr * sn[d]);
        const size_t oidx = (((size_t)(b*HH + h)) * SS + s) * DD + d;
        qO[oidx] = qv;
        kO[oidx] = kvb[(size_t)row * (HH*2*DD) + h*256 + d] + krot[d];
        vO[oidx] = kvb[(size_t)row * (HH*2*DD) + h*256 + 128 + d];
    }
}

// ---------------- flash attention (fp32, causal) ------------------------------
#define FLASH_SMEM_FLOATS (128*65*2 + 64*128 + 64*68 + 64*3)
#define FLASH_SMEM_BYTES  (FLASH_SMEM_FLOATS * 4)

__global__ __launch_bounds__(128) void flash_attn(const float* __restrict__ Q,
                                                  const float* __restrict__ Kg,
                                                  const float* __restrict__ Vg,
                                                  float* __restrict__ O)
{
    const int mt = blockIdx.x;
    const int bh = blockIdx.y;
    const int b = bh >> 4, h = bh & 15;
    const int tid = threadIdx.x;
    const int w = tid >> 5, lane = tid & 31;
    const int lr = lane >> 3, lc = lane & 7;
    const int i0 = w*16 + lr*4;
    const int j0 = lc*8;

    extern __shared__ float smf[];
    float* QsT = smf;                   // [128][65]
    float* KsT = QsT + 128*65;          // [128][65]
    float* Vs  = KsT + 128*65;          // [64][128]
    float* Ps  = Vs  + 64*128;          // [64][68]
    float* m_s    = Ps + 64*68;
    float* se_s   = m_s + 64;
    float* corr_s = se_s + 64;

    const float* Qb = Q + ((size_t)bh * SS + mt*64) * DD;
    for (int t = tid; t < 64*32; t += 128) {
        const int i = t >> 5;
        const int c4 = (t & 31) << 2;
        float4 v = *(const float4*)(Qb + (size_t)i*DD + c4);
        QsT[(c4+0)*65 + i] = v.x;
        QsT[(c4+1)*65 + i] = v.y;
        QsT[(c4+2)*65 + i] = v.z;
        QsT[(c4+3)*65 + i] = v.w;
    }
    if (tid < 64) { m_s[tid] = -1e30f; se_s[tid] = 0.f; }

    float acc[4][16];
#pragma unroll
    for (int a = 0; a < 4; a++)
#pragma unroll
        for (int c = 0; c < 16; c++) acc[a][c] = 0.f;

    for (int nt = 0; nt <= mt; nt++) {
        __syncthreads();
        const float* Kb = Kg + ((size_t)bh * SS + nt*64) * DD;
        const float* Vb = Vg + ((size_t)bh * SS + nt*64) * DD;
        for (int t = tid; t < 64*32; t += 128) {
            const int i = t >> 5;
            const int c4 = (t & 31) << 2;
            float4 v = *(const float4*)(Kb + (size_t)i*DD + c4);
            KsT[(c4+0)*65 + i] = v.x;
            KsT[(c4+1)*65 + i] = v.y;
            KsT[(c4+2)*65 + i] = v.z;
            KsT[(c4+3)*65 + i] = v.w;
            float4 u = *(const float4*)(Vb + (size_t)i*DD + c4);
            *(float4*)(Vs + i*128 + c4) = u;
        }
        __syncthreads();

        float s[4][8];
#pragma unroll
        for (int a = 0; a < 4; a++)
#pragma unroll
            for (int c = 0; c < 8; c++) s[a][c] = 0.f;
        for (int k = 0; k < 128; k++) {
            float qr_[4], kr_[8];
#pragma unroll
            for (int a = 0; a < 4; a++) qr_[a] = QsT[k*65 + i0 + a];
#pragma unroll
            for (int c = 0; c < 8; c++) kr_[c] = KsT[k*65 + j0 + c];
#pragma unroll
            for (int a = 0; a < 4; a++)
#pragma unroll
                for (int c = 0; c < 8; c++) s[a][c] = fmaf(qr_[a], kr_[c], s[a][c]);
        }
        const bool diag = (nt == mt);
#pragma unroll
        for (int a = 0; a < 4; a++) {
            const int gi = i0 + a;
#pragma unroll
            for (int c = 0; c < 8; c++) {
                const int gj = j0 + c;
                float v = s[a][c] * ATT_SCALE;
                if (diag && gj > gi) v = -1e30f;
                Ps[gi*68 + gj] = v;
            }
        }
        __syncthreads();

        {
            const int rr   = tid & 63;
            const int half = tid >> 6;
            float* prow = Ps + rr*68 + half*32;
            float rmax = -1e30f;
#pragma unroll 8
            for (int j = 0; j < 32; j++) rmax = fmaxf(rmax, prow[j]);
            __shared__ float hmax[128], hsum[128];
            hmax[tid] = rmax;
            __syncthreads();
            const float mold = m_s[rr];
            const float rowmax = fmaxf(fmaxf(hmax[rr], hmax[rr + 64]), mold);
            float sum = 0.f;
#pragma unroll 8
            for (int j = 0; j < 32; j++) {
                const float p = expf(prow[j] - rowmax);
                prow[j] = p;
                sum += p;
            }
            hsum[tid] = sum;
            __syncthreads();
            if (tid < 64) {
                const float corr = expf(mold - rowmax);
                se_s[rr] = se_s[rr] * corr + hsum[rr] + hsum[rr + 64];
                m_s[rr] = rowmax;
                corr_s[rr] = corr;
            }
        }
        __syncthreads();

        float cr[4];
#pragma unroll
        for (int a = 0; a < 4; a++) cr[a] = corr_s[i0 + a];
#pragma unroll
        for (int a = 0; a < 4; a++)
#pragma unroll
            for (int c = 0; c < 16; c++) acc[a][c] *= cr[a];

        for (int j = 0; j < 64; j++) {
            float p[4];
#pragma unroll
            for (int a = 0; a < 4; a++) p[a] = Ps[(i0 + a)*68 + j];
#pragma unroll
            for (int q = 0; q < 4; q++) {
                const float4 vv = *(const float4*)(Vs + j*128 + lc*4 + q*32);
#pragma unroll
                for (int a = 0; a < 4; a++) {
                    acc[a][q*4+0] = fmaf(p[a], vv.x, acc[a][q*4+0]);
                    acc[a][q*4+1] = fmaf(p[a], vv.y, acc[a][q*4+1]);
                    acc[a][q*4+2] = fmaf(p[a], vv.z, acc[a][q*4+2]);
                    acc[a][q*4+3] = fmaf(p[a], vv.w, acc[a][q*4+3]);
                }
            }
        }
    }
    __syncthreads();

#pragma unroll
    for (int a = 0; a < 4; a++) {
        const int gi = i0 + a;
        const float inv = 1.f / (se_s[gi] + 1e-5f);
        const int row = b*SS + mt*64 + gi;
        float* Ob = O + (size_t)row * (HH*DD) + h*DD;
#pragma unroll
        for (int q = 0; q < 4; q++) {
            float4 o;
            o.x = acc[a][q*4+0] * inv;
            o.y = acc[a][q*4+1] * inv;
            o.z = acc[a][q*4+2] * inv;
            o.w = acc[a][q*4+3] * inv;
            *(float4*)(Ob + lc*4 + q*32) = o;
        }
    }
}

// ---------------- launch --------------------------------------------------------
extern "C" void kernel_launch(void* const* d_in, const int* in_sizes, int n_in,
                              void* d_out, int out_size)
{
    const float* hidden = (const float*)d_in[0];
    const int*   pos    = (const int*)  d_in[1];
    const float* w_q    = (const float*)d_in[2];
    const float* w_kv_a = (const float*)d_in[3];
    const float* w_kv_b = (const float*)d_in[4];
    const float* w_o    = (const float*)d_in[5];
    const float* kv_ln  = (const float*)d_in[6];
    float* out = (float*)d_out;

    float *q, *kva, *ckv, *kvb, *qr, *kk, *vv, *attn;
    cudaGetSymbolAddress((void**)&q,    g_q);
    cudaGetSymbolAddress((void**)&kva,  g_kva);
    cudaGetSymbolAddress((void**)&ckv,  g_ckv);
    cudaGetSymbolAddress((void**)&kvb,  g_kvb);
    cudaGetSymbolAddress((void**)&qr,   g_qr);
    cudaGetSymbolAddress((void**)&kk,   g_k);
    cudaGetSymbolAddress((void**)&vv,   g_v);
    cudaGetSymbolAddress((void**)&attn, g_attn);

    __nv_bfloat16 *ah, *al, *ckvh, *ckvl, *bqh, *bql, *bkah, *bkal, *bkbh, *bkbl, *boh, *bol;
    cudaGetSymbolAddress((void**)&ah,   g_ah);
    cudaGetSymbolAddress((void**)&al,   g_al);
    cudaGetSymbolAddress((void**)&ckvh, g_ckvh);
    cudaGetSymbolAddress((void**)&ckvl, g_ckvl);
    cudaGetSymbolAddress((void**)&bqh,  g_bqh);
    cudaGetSymbolAddress((void**)&bql,  g_bql);
    cudaGetSymbolAddress((void**)&bkah, g_bkah);
    cudaGetSymbolAddress((void**)&bkal, g_bkal);
    cudaGetSymbolAddress((void**)&bkbh, g_bkbh);
    cudaGetSymbolAddress((void**)&bkbl, g_bkbl);
    cudaGetSymbolAddress((void**)&boh,  g_boh);
    cudaGetSymbolAddress((void**)&bol,  g_bol);

    cudaFuncSetAttribute(hgemm, cudaFuncAttributeMaxDynamicSharedMemorySize, HG_SMEM);
    cudaFuncSetAttribute(flash_attn, cudaFuncAttributeMaxDynamicSharedMemorySize,
                         FLASH_SMEM_BYTES);

    // weight conversions (transpose+split):  X[K,N] -> Bt[N,K]
    split_T<<<dim3(HH*DD/32, HID/32),   256>>>(w_q,    bqh,  bql,  HID,  HH*DD);
    split_T<<<dim3(KVA_N/32, HID/32),   256>>>(w_kv_a, bkah, bkal, HID,  KVA_N);
    split_T<<<dim3(HH*2*DD/32, RANK/32),256>>>(w_kv_b, bkbh, bkbl, RANK, HH*2*DD);
    split_T<<<dim3(HID/32, HH*DD/32),   256>>>(w_o,    boh,  bol,  HH*DD, HID);
    // hidden split
    split_rows<<<(BS*HID/4 + 255)/256, 256>>>(hidden, ah, al, BS*HID/4);

    // 1. q = hidden @ w_q
    hgemm<<<dim3((HH*DD)/128, BS/128), 256, HG_SMEM>>>(ah, al, bqh, bql, q, BS, HH*DD, HID);
    // 2. kv_a = hidden @ w_kv_a
    hgemm<<<dim3(KVA_N/128, BS/128), 256, HG_SMEM>>>(ah, al, bkah, bkal, kva, BS, KVA_N, HID);
    // 3. RMSNorm
    rmsnorm_k<<<BS, 256>>>(kva, kv_ln, ckv);
    // 4. kv = c_kv @ w_kv_b
    split_rows<<<(BS*RANK/4 + 255)/256, 256>>>(ckv, ckvh, ckvl, BS*RANK/4);
    hgemm<<<dim3((HH*2*DD)/128, BS/128), 256, HG_SMEM>>>(ckvh, ckvl, bkbh, bkbl, kvb,
                                                         BS, HH*2*DD, RANK);
    // 5. RoPE + assemble
    rope_combine<<<BS, 256>>>(q, kva, kvb, pos, qr, kk, vv);
    // 6. flash attention
    flash_attn<<<dim3(SS/64, BB*HH), 128, FLASH_SMEM_BYTES>>>(qr, kk, vv, attn);
    // 7. out = attn @ w_o   (reuse ah/al buffers)
    split_rows<<<(BS*(HH*DD)/4 + 255)/256, 256>>>(attn, ah, al, BS*(HH*DD)/4);
    hgemm<<<dim3(HID/128, BS/128), 256, HG_SMEM>>>(ah, al, boh, bol, out, BS, HID, HH*DD);
}

// round 6
// speedup vs baseline: 2.2103x; 1.6407x over previous
#include <cuda_runtime.h>
#include <cuda_bf16.h>
#include <math.h>
#include <stdint.h>

// Problem constants
#define BB 2
#define SS 2048
#define HID 2048
#define HH 16
#define DD 128
#define RANK 512
#define BS (BB*SS)          // 4096
#define KVA_N (RANK + DD)   // 640
#define MSCALE 1.2772588722239782f
#define ATT_SCALE 0.08838834764831845f  // 1/sqrt(128)

// ---------------- scratch (device globals; no allocation allowed) -------------
__device__ float g_q[BS * (HH*DD)];
__device__ float g_kva[BS * KVA_N];
__device__ float g_ckv[BS * RANK];
__device__ float g_kvb[BS * (HH*2*DD)];
__device__ float g_attn[BS * (HH*DD)];

// bf16 q/k/v hi/lo for tensor-core flash attention  [B,H,S,D]
#define QKV_ELEMS (BB*HH*SS*DD)
__device__ __nv_bfloat16 g_fqh[QKV_ELEMS], g_fql[QKV_ELEMS];
__device__ __nv_bfloat16 g_fkh[QKV_ELEMS], g_fkl[QKV_ELEMS];
__device__ __nv_bfloat16 g_fvh[QKV_ELEMS], g_fvl[QKV_ELEMS];

// bf16 split operands (hi/lo). g_ah/g_al reused: hidden first, then attn.
__device__ __nv_bfloat16 g_ah[BS*HID],  g_al[BS*HID];
__device__ __nv_bfloat16 g_ckvh[BS*RANK], g_ckvl[BS*RANK];
__device__ __nv_bfloat16 g_bqh[HID*HH*DD],   g_bql[HID*HH*DD];
__device__ __nv_bfloat16 g_bkah[KVA_N*HID],  g_bkal[KVA_N*HID];
__device__ __nv_bfloat16 g_bkbh[HH*2*DD*RANK], g_bkbl[HH*2*DD*RANK];
__device__ __nv_bfloat16 g_boh[HID*HH*DD],   g_bol[HID*HH*DD];

// =================== base-ISA helpers (compile for plain sm_103) ==============
__device__ __forceinline__ uint32_t smem_u32(const void* p) {
    uint32_t a;
    asm("{ .reg .u64 t; cvta.to.shared.u64 t, %1; cvt.u32.u64 %0, t; }"
        : "=r"(a) : "l"(p));
    return a;
}

#define CP_ASYNC16(dst, src) \
    asm volatile("cp.async.cg.shared.global [%0], [%1], 16;" :: "r"(dst), "l"(src))
#define CP_COMMIT() asm volatile("cp.async.commit_group;" ::: "memory")
#define CP_WAIT(n)  asm volatile("cp.async.wait_group %0;" :: "n"(n) : "memory")

__device__ __forceinline__ void ldm_x4(uint32_t a, uint32_t& r0, uint32_t& r1,
                                       uint32_t& r2, uint32_t& r3) {
    asm volatile("ldmatrix.sync.aligned.m8n8.x4.shared.b16 {%0,%1,%2,%3}, [%4];"
                 : "=r"(r0), "=r"(r1), "=r"(r2), "=r"(r3) : "r"(a));
}
__device__ __forceinline__ void ldm_x4t(uint32_t a, uint32_t& r0, uint32_t& r1,
                                        uint32_t& r2, uint32_t& r3) {
    asm volatile("ldmatrix.sync.aligned.m8n8.x4.trans.shared.b16 {%0,%1,%2,%3}, [%4];"
                 : "=r"(r0), "=r"(r1), "=r"(r2), "=r"(r3) : "r"(a));
}

__device__ __forceinline__ void mma_bf16(float* d, const uint32_t* a, const uint32_t* b) {
    asm volatile(
        "mma.sync.aligned.m16n8k16.row.col.f32.bf16.bf16.f32 "
        "{%0,%1,%2,%3}, {%4,%5,%6,%7}, {%8,%9}, {%0,%1,%2,%3};"
        : "+f"(d[0]), "+f"(d[1]), "+f"(d[2]), "+f"(d[3])
        : "r"(a[0]), "r"(a[1]), "r"(a[2]), "r"(a[3]), "r"(b[0]), "r"(b[1]));
}

__device__ __forceinline__ uint32_t pack_bf16(float lo, float hi) {
    __nv_bfloat162 t = __floats2bfloat162_rn(lo, hi);
    return *reinterpret_cast<uint32_t*>(&t);
}

// =================== split-bf16 tensor GEMM (mma.sync) ========================
#define KB_BYTES    6144
#define OP_BYTES    12288
#define STAGE_BYTES 49152
#define HG_SMEM     (2*STAGE_BYTES)

__global__ __launch_bounds__(256) void hgemm(const __nv_bfloat16* __restrict__ Ah,
                                             const __nv_bfloat16* __restrict__ Al,
                                             const __nv_bfloat16* __restrict__ Bh,
                                             const __nv_bfloat16* __restrict__ Bl,
                                             float* __restrict__ C,
                                             int M, int N, int K)
{
    extern __shared__ char sm[];
    const uint32_t sb = smem_u32(sm);
    const int tid = threadIdx.x;
    const int wid = tid >> 5, lane = tid & 31;
    const int wm = wid >> 2, wn = wid & 3;
    const int bx = blockIdx.x, by = blockIdx.y;

    const int r = lane & 7, grp = lane >> 3;
    const int a_row_off = ((grp & 1) << 3) + r;
    const int a_par     = grp >> 1;
    const int b_row_off = ((grp >> 1) << 3) + r;
    const int b_par     = grp & 1;

    const __nv_bfloat16* srcs[4] = {
        Ah + (size_t)by*128*K, Al + (size_t)by*128*K,
        Bh + (size_t)bx*128*K, Bl + (size_t)bx*128*K };

    float acc[4][4][4];
#pragma unroll
    for (int mt = 0; mt < 4; mt++)
#pragma unroll
        for (int nt = 0; nt < 4; nt++)
#pragma unroll
            for (int e = 0; e < 4; e++) acc[mt][nt][e] = 0.f;

    auto issue = [&](int c, int st) {
#pragma unroll
        for (int i = 0; i < 8; i++) {
            const int op  = i >> 1;
            const int idx = tid + (i & 1)*256;
            const int row = idx >> 2, j = idx & 3;
            const __nv_bfloat16* s = srcs[op] + (size_t)row*K + c*32 + j*8;
            const uint32_t d = sb + st*STAGE_BYTES + op*OP_BYTES
                             + (j >> 1)*KB_BYTES + row*48 + (j & 1)*16;
            CP_ASYNC16(d, s);
        }
        CP_COMMIT();
    };

    const int NC = K >> 5;
    issue(0, 0);

    for (int c = 0; c < NC; c++) {
        const int st = c & 1;
        if (c + 1 < NC) { issue(c + 1, st ^ 1); CP_WAIT(1); }
        else            { CP_WAIT(0); }
        __syncthreads();

        const uint32_t sst = sb + st*STAGE_BYTES;
#pragma unroll
        for (int kb = 0; kb < 2; kb++) {
            uint32_t Bfh[4][2], Bfl[4][2];
#pragma unroll
            for (int np = 0; np < 2; np++) {
                const uint32_t ba = sst + 2*OP_BYTES + kb*KB_BYTES
                                  + (wn*32 + np*16 + b_row_off)*48 + b_par*16;
                ldm_x4(ba, Bfh[np*2][0], Bfh[np*2][1], Bfh[np*2+1][0], Bfh[np*2+1][1]);
                ldm_x4(ba + OP_BYTES,
                       Bfl[np*2][0], Bfl[np*2][1], Bfl[np*2+1][0], Bfl[np*2+1][1]);
            }
#pragma unroll
            for (int mt = 0; mt < 4; mt++) {
                const uint32_t aa = sst + kb*KB_BYTES
                                  + (wm*64 + mt*16 + a_row_off)*48 + a_par*16;
                uint32_t Afh[4], Afl[4];
                ldm_x4(aa, Afh[0], Afh[1], Afh[2], Afh[3]);
                ldm_x4(aa + OP_BYTES, Afl[0], Afl[1], Afl[2], Afl[3]);
#pragma unroll
                for (int nt = 0; nt < 4; nt++) {
                    mma_bf16(acc[mt][nt], Afh, Bfh[nt]);
                    mma_bf16(acc[mt][nt], Afh, Bfl[nt]);
                    mma_bf16(acc[mt][nt], Afl, Bfh[nt]);
                }
            }
        }
        __syncthreads();
    }

    const int tq = lane >> 2, tr = lane & 3;
#pragma unroll
    for (int mt = 0; mt < 4; mt++) {
#pragma unroll
        for (int nt = 0; nt < 4; nt++) {
            const int m0 = by*128 + wm*64 + mt*16 + tq;
            const int n0 = bx*128 + wn*32 + nt*8 + tr*2;
            float2 v0 = make_float2(acc[mt][nt][0], acc[mt][nt][1]);
            float2 v1 = make_float2(acc[mt][nt][2], acc[mt][nt][3]);
            *(float2*)(C + (size_t)m0*N + n0)       = v0;
            *(float2*)(C + (size_t)(m0+8)*N + n0)   = v1;
        }
    }
}

// =================== bf16 split conversions ====================================
__global__ __launch_bounds__(256) void split_rows(const float* __restrict__ X,
                                                  __nv_bfloat16* __restrict__ H,
                                                  __nv_bfloat16* __restrict__ L,
                                                  int n4)
{
    const int i = blockIdx.x*256 + threadIdx.x;
    if (i >= n4) return;
    float4 v = ((const float4*)X)[i];
    __nv_bfloat16 h0 = __float2bfloat16(v.x), h1 = __float2bfloat16(v.y);
    __nv_bfloat16 h2 = __float2bfloat16(v.z), h3 = __float2bfloat16(v.w);
    __nv_bfloat16 l0 = __float2bfloat16(v.x - __bfloat162float(h0));
    __nv_bfloat16 l1 = __float2bfloat16(v.y - __bfloat162float(h1));
    __nv_bfloat16 l2 = __float2bfloat16(v.z - __bfloat162float(h2));
    __nv_bfloat16 l3 = __float2bfloat16(v.w - __bfloat162float(h3));
    ((__nv_bfloat162*)H)[i*2+0] = __nv_bfloat162(h0, h1);
    ((__nv_bfloat162*)H)[i*2+1] = __nv_bfloat162(h2, h3);
    ((__nv_bfloat162*)L)[i*2+0] = __nv_bfloat162(l0, l1);
    ((__nv_bfloat162*)L)[i*2+1] = __nv_bfloat162(l2, l3);
}

// transpose+split: X[Kd,Nd] fp32 -> H,L bf16 [Nd,Kd]
__global__ __launch_bounds__(256) void split_T(const float* __restrict__ X,
                                               __nv_bfloat16* __restrict__ H,
                                               __nv_bfloat16* __restrict__ L,
                                               int Kd, int Nd)
{
    __shared__ float t[32][33];
    const int tx = threadIdx.x & 31, ty = threadIdx.x >> 5;
    const int c0 = blockIdx.x*32, r0 = blockIdx.y*32;
#pragma unroll
    for (int i = 0; i < 4; i++)
        t[ty + i*8][tx] = X[(size_t)(r0 + ty + i*8)*Nd + c0 + tx];
    __syncthreads();
#pragma unroll
    for (int i = 0; i < 4; i++) {
        const float x = t[tx][ty + i*8];
        const __nv_bfloat16 h = __float2bfloat16(x);
        const __nv_bfloat16 l = __float2bfloat16(x - __bfloat162float(h));
        const size_t o = (size_t)(c0 + ty + i*8)*Kd + r0 + tx;
        H[o] = h; L[o] = l;
    }
}

// ---------------- RMSNorm over first 512 cols of kv_a -------------------------
__global__ __launch_bounds__(256) void rmsnorm_k(const float* __restrict__ kva,
                                                 const float* __restrict__ w,
                                                 float* __restrict__ out)
{
    const int row = blockIdx.x;
    const float* x = kva + (size_t)row * KVA_N;
    float s = 0.f;
    for (int i = threadIdx.x; i < RANK; i += 256) { float v = x[i]; s = fmaf(v, v, s); }
#pragma unroll
    for (int o = 16; o; o >>= 1) s += __shfl_xor_sync(0xffffffffu, s, o);
    __shared__ float red[8];
    __shared__ float inv_s;
    if ((threadIdx.x & 31) == 0) red[threadIdx.x >> 5] = s;
    __syncthreads();
    if (threadIdx.x == 0) {
        float t = 0.f;
#pragma unroll
        for (int i = 0; i < 8; i++) t += red[i];
        inv_s = rsqrtf(t * (1.f/512.f) + 1e-6f);
    }
    __syncthreads();
    const float inv = inv_s;
    for (int i = threadIdx.x; i < RANK; i += 256)
        out[(size_t)row * RANK + i] = w[i] * (x[i] * inv);
}

// ------- YaRN RoPE + k/v assembly; emits bf16 hi/lo (q pre-scaled) ------------
__global__ __launch_bounds__(256) void rope_combine(const float* __restrict__ qpre,
                                                    const float* __restrict__ kva,
                                                    const float* __restrict__ kvb,
                                                    const int*   __restrict__ pos_ids,
                                                    __nv_bfloat16* __restrict__ qh,
                                                    __nv_bfloat16* __restrict__ ql,
                                                    __nv_bfloat16* __restrict__ kh,
                                                    __nv_bfloat16* __restrict__ kl,
                                                    __nv_bfloat16* __restrict__ vh,
                                                    __nv_bfloat16* __restrict__ vl)
{
    const int row = blockIdx.x;
    const int b = row >> 11;
    const int s = row & 2047;
    const int tid = threadIdx.x;

    __shared__ float cs[128], sn[128], krot[128];
    const float pos = (float)pos_ids[row];

    if (tid < 128) {
        const int j = tid & 63;
        const float fj = (float)j;
        const float extrap = expf(-fj * 0.015625f * 13.122363377404328f);
        float smooth = (fj - 18.f) * (1.f / 17.f);
        smooth = fminf(fmaxf(smooth, 0.f), 1.f);
        const float invf = extrap * ((1.f - smooth) * 0.0625f + smooth);
        const float fr = pos * invf;
        cs[tid] = cosf(fr) * MSCALE;
        sn[tid] = sinf(fr) * MSCALE;
        krot[tid] = kva[(size_t)row * KVA_N + RANK + tid];
    }
    __syncthreads();
    float kv_ = 0.f;
    if (tid < 128) {
        const int d = tid;
        const float x = krot[d];
        const float pr = (d < 64) ? -krot[d + 64] : krot[d - 64];
        kv_ = fmaf(x, cs[d], pr * sn[d]);
    }
    __syncthreads();
    if (tid < 128) krot[tid] = kv_;
    __syncthreads();

    for (int e = tid; e < HH*DD; e += 256) {
        const int h = e >> 7, d = e & 127;
        const float x  = qpre[(size_t)row * (HH*DD) + e];
        const float pr = qpre[(size_t)row * (HH*DD) + h*128 + ((d < 64) ? d + 64 : d - 64)];
        const float qv = (d < 64) ? fmaf(x, cs[d], -pr * sn[d])
                                  : fmaf(x, cs[d],  pr * sn[d]);
        const float kvv = kvb[(size_t)row * (HH*2*DD) + h*256 + d] + krot[d];
        const float vvv = kvb[(size_t)row * (HH*2*DD) + h*256 + 128 + d];
        const size_t oidx = (((size_t)(b*HH + h)) * SS + s) * DD + d;

        const float qs = qv * ATT_SCALE;
        __nv_bfloat16 a = __float2bfloat16(qs);
        qh[oidx] = a; ql[oidx] = __float2bfloat16(qs - __bfloat162float(a));
        a = __float2bfloat16(kvv);
        kh[oidx] = a; kl[oidx] = __float2bfloat16(kvv - __bfloat162float(a));
        a = __float2bfloat16(vvv);
        vh[oidx] = a; vl[oidx] = __float2bfloat16(vvv - __bfloat162float(a));
    }
}

// ---------------- tensor-core flash attention (split-bf16, causal) ------------
// BM=64 (4 warps x m16), BN=64, D=128. 272B-padded smem rows (conflict-free ldmatrix).
// K/V double-buffered via cp.async groups.
#define FA_STRIDE 272
#define FA_TILE   (64*FA_STRIDE)       // 17408
#define FA_SMEM   (10*FA_TILE)         // Qh,Ql + 2 x (Kh,Kl,Vh,Vl)

__global__ __launch_bounds__(128) void flash_mma(const __nv_bfloat16* __restrict__ Qh_,
                                                 const __nv_bfloat16* __restrict__ Ql_,
                                                 const __nv_bfloat16* __restrict__ Kh_,
                                                 const __nv_bfloat16* __restrict__ Kl_,
                                                 const __nv_bfloat16* __restrict__ Vh_,
                                                 const __nv_bfloat16* __restrict__ Vl_,
                                                 float* __restrict__ O)
{
    const int mt = blockIdx.x;   // query tile (0..31)
    const int bh = blockIdx.y;   // b*H+h
    const int b = bh >> 4, h = bh & 15;
    const int tid = threadIdx.x;
    const int wid = tid >> 5, lane = tid & 31;
    const int grp = lane >> 3, r8 = lane & 7;
    const int tq = lane >> 2, tr = lane & 3;

    extern __shared__ char smc[];
    const uint32_t sb  = smem_u32(smc);
    const uint32_t sQh = sb, sQl = sb + FA_TILE;

    // load Q tiles (group 0)
    const size_t qoff = ((size_t)bh*SS + (size_t)mt*64)*DD;
    {
        const __nv_bfloat16* s0 = Qh_ + qoff;
        const __nv_bfloat16* s1 = Ql_ + qoff;
#pragma unroll
        for (int i = 0; i < 8; i++) {
            const int idx = tid + i*128;
            const int row = idx >> 4, ch = idx & 15;
            CP_ASYNC16(sQh + row*FA_STRIDE + ch*16, s0 + row*128 + ch*8);
            CP_ASYNC16(sQl + row*FA_STRIDE + ch*16, s1 + row*128 + ch*8);
        }
        CP_COMMIT();
    }

    auto issueKV = [&](int nt, int st) {
        const size_t koff = ((size_t)bh*SS + (size_t)nt*64)*DD;
        const __nv_bfloat16* srcs[4] = {Kh_+koff, Kl_+koff, Vh_+koff, Vl_+koff};
        const uint32_t base = sb + 2*FA_TILE + st*4*FA_TILE;
#pragma unroll
        for (int t4 = 0; t4 < 4; t4++) {
            const uint32_t dt = base + t4*FA_TILE;
            const __nv_bfloat16* s = srcs[t4];
#pragma unroll
            for (int i = 0; i < 8; i++) {
                const int idx = tid + i*128;
                const int row = idx >> 4, ch = idx & 15;
                CP_ASYNC16(dt + row*FA_STRIDE + ch*16, s + row*128 + ch*8);
            }
        }
        CP_COMMIT();
    };

    float o[16][4];
#pragma unroll
    for (int j = 0; j < 16; j++)
#pragma unroll
        for (int e = 0; e < 4; e++) o[j][e] = 0.f;
    float mrow0 = -1e30f, mrow1 = -1e30f, se0 = 0.f, se1 = 0.f;

    // fragment address components
    const uint32_t a_row   = wid*16 + ((grp & 1) << 3) + r8;   // Q rows
    const uint32_t a_par   = (grp >> 1);                       // k 16B half
    const uint32_t b_row   = ((grp >> 1) << 3) + r8;           // K rows (n)
    const uint32_t b_par   = (grp & 1);
    const uint32_t v_krow  = ((grp & 1) << 3) + r8;            // V k rows
    const uint32_t v_ncol  = ((grp >> 1) << 3);                // V n col offset

    issueKV(0, 0);

    for (int nt = 0; nt <= mt; nt++) {
        const int st = nt & 1;
        __syncthreads();                       // readers of buf st^1 done
        if (nt < mt) { issueKV(nt + 1, st ^ 1); CP_WAIT(1); }
        else         { CP_WAIT(0); }
        __syncthreads();

        const uint32_t sKh = sb + 2*FA_TILE + st*4*FA_TILE;
        const uint32_t sKl = sKh + FA_TILE;
        const uint32_t sVh = sKl + FA_TILE;
        const uint32_t sVl = sVh + FA_TILE;

        // ---- scores S = Q K^T (3-term split) ----
        float s[8][4];
#pragma unroll
        for (int j = 0; j < 8; j++)
#pragma unroll
            for (int e = 0; e < 4; e++) s[j][e] = 0.f;

#pragma unroll
        for (int k = 0; k < 8; k++) {
            uint32_t qfh[4], qfl[4];
            const uint32_t qa = sQh + a_row*FA_STRIDE + k*32 + a_par*16;
            ldm_x4(qa, qfh[0], qfh[1], qfh[2], qfh[3]);
            ldm_x4(qa + FA_TILE, qfl[0], qfl[1], qfl[2], qfl[3]);
#pragma unroll
            for (int p = 0; p < 4; p++) {
                uint32_t kfh[2][2], kfl[2][2];
                const uint32_t ka = sKh + (p*16 + b_row)*FA_STRIDE + k*32 + b_par*16;
                ldm_x4(ka, kfh[0][0], kfh[0][1], kfh[1][0], kfh[1][1]);
                ldm_x4(ka + FA_TILE, kfl[0][0], kfl[0][1], kfl[1][0], kfl[1][1]);
                mma_bf16(s[2*p],   qfh, kfh[0]);
                mma_bf16(s[2*p],   qfh, kfl[0]);
                mma_bf16(s[2*p],   qfl, kfh[0]);
                mma_bf16(s[2*p+1], qfh, kfh[1]);
                mma_bf16(s[2*p+1], qfh, kfl[1]);
                mma_bf16(s[2*p+1], qfl, kfh[1]);
            }
        }

        // ---- causal mask on diagonal tile ----
        if (nt == mt) {
            const int gi0 = mt*64 + wid*16 + tq;
            const int gi1 = gi0 + 8;
#pragma unroll
            for (int j = 0; j < 8; j++) {
                const int gj0 = nt*64 + j*8 + tr*2;
                if (gj0     > gi0) s[j][0] = -1e30f;
                if (gj0 + 1 > gi0) s[j][1] = -1e30f;
                if (gj0     > gi1) s[j][2] = -1e30f;
                if (gj0 + 1 > gi1) s[j][3] = -1e30f;
            }
        }

        // ---- online softmax in fragment layout ----
        float mx0 = -1e30f, mx1 = -1e30f;
#pragma unroll
        for (int j = 0; j < 8; j++) {
            mx0 = fmaxf(mx0, fmaxf(s[j][0], s[j][1]));
            mx1 = fmaxf(mx1, fmaxf(s[j][2], s[j][3]));
        }
        mx0 = fmaxf(mx0, __shfl_xor_sync(0xffffffffu, mx0, 1));
        mx0 = fmaxf(mx0, __shfl_xor_sync(0xffffffffu, mx0, 2));
        mx1 = fmaxf(mx1, __shfl_xor_sync(0xffffffffu, mx1, 1));
        mx1 = fmaxf(mx1, __shfl_xor_sync(0xffffffffu, mx1, 2));
        const float nm0 = fmaxf(mrow0, mx0);
        const float nm1 = fmaxf(mrow1, mx1);
        const float c0 = expf(mrow0 - nm0);
        const float c1 = expf(mrow1 - nm1);
        float sum0 = 0.f, sum1 = 0.f;
#pragma unroll
        for (int j = 0; j < 8; j++) {
            s[j][0] = expf(s[j][0] - nm0); sum0 += s[j][0];
            s[j][1] = expf(s[j][1] - nm0); sum0 += s[j][1];
            s[j][2] = expf(s[j][2] - nm1); sum1 += s[j][2];
            s[j][3] = expf(s[j][3] - nm1); sum1 += s[j][3];
        }
        sum0 += __shfl_xor_sync(0xffffffffu, sum0, 1);
        sum0 += __shfl_xor_sync(0xffffffffu, sum0, 2);
        sum1 += __shfl_xor_sync(0xffffffffu, sum1, 1);
        sum1 += __shfl_xor_sync(0xffffffffu, sum1, 2);
        se0 = se0 * c0 + sum0;
        se1 = se1 * c1 + sum1;
        mrow0 = nm0; mrow1 = nm1;
#pragma unroll
        for (int j = 0; j < 16; j++) {
            o[j][0] *= c0; o[j][1] *= c0;
            o[j][2] *= c1; o[j][3] *= c1;
        }

        // ---- P -> bf16 hi/lo A-fragments (C-frag layout identity) ----
        uint32_t ph[4][4], pl[4][4];
#pragma unroll
        for (int t = 0; t < 4; t++) {
#pragma unroll
            for (int hf = 0; hf < 2; hf++) {
                const int tile = 2*t + hf;
                const float p0 = s[tile][0], p1 = s[tile][1];
                const float p2 = s[tile][2], p3 = s[tile][3];
                const __nv_bfloat16 h0 = __float2bfloat16(p0);
                const __nv_bfloat16 h1 = __float2bfloat16(p1);
                const __nv_bfloat16 h2 = __float2bfloat16(p2);
                const __nv_bfloat16 h3 = __float2bfloat16(p3);
                ph[t][2*hf+0] = pack_bf16(__bfloat162float(h0), __bfloat162float(h1));
                ph[t][2*hf+1] = pack_bf16(__bfloat162float(h2), __bfloat162float(h3));
                pl[t][2*hf+0] = pack_bf16(p0 - __bfloat162float(h0),
                                          p1 - __bfloat162float(h1));
                pl[t][2*hf+1] = pack_bf16(p2 - __bfloat162float(h2),
                                          p3 - __bfloat162float(h3));
            }
        }

        // ---- O += P V (3-term split), V via ldmatrix.trans ----
#pragma unroll
        for (int t = 0; t < 4; t++) {
#pragma unroll
            for (int p = 0; p < 8; p++) {
                uint32_t vfh[2][2], vfl[2][2];
                const uint32_t va = sVh + (t*16 + v_krow)*FA_STRIDE
                                  + (p*16 + v_ncol)*2;
                ldm_x4t(va, vfh[0][0], vfh[0][1], vfh[1][0], vfh[1][1]);
                ldm_x4t(va + FA_TILE, vfl[0][0], vfl[0][1], vfl[1][0], vfl[1][1]);
                mma_bf16(o[2*p],   ph[t], vfh[0]);
                mma_bf16(o[2*p],   ph[t], vfl[0]);
                mma_bf16(o[2*p],   pl[t], vfh[0]);
                mma_bf16(o[2*p+1], ph[t], vfh[1]);
                mma_bf16(o[2*p+1], ph[t], vfl[1]);
                mma_bf16(o[2*p+1], pl[t], vfh[1]);
            }
        }
    }

    // ---- epilogue ----
    const float i0 = 1.f / (se0 + 1e-5f);
    const float i1 = 1.f / (se1 + 1e-5f);
    const int s0 = mt*64 + wid*16 + tq;
    float* O0 = O + ((size_t)(b*SS + s0))*(HH*DD) + h*DD;
    float* O1 = O0 + (size_t)8*(HH*DD);
#pragma unroll
    for (int j = 0; j < 16; j++) {
        *(float2*)(O0 + j*8 + tr*2) = make_float2(o[j][0]*i0, o[j][1]*i0);
        *(float2*)(O1 + j*8 + tr*2) = make_float2(o[j][2]*i1, o[j][3]*i1);
    }
}

// ---------------- launch --------------------------------------------------------
extern "C" void kernel_launch(void* const* d_in, const int* in_sizes, int n_in,
                              void* d_out, int out_size)
{
    const float* hidden = (const float*)d_in[0];
    const int*   pos    = (const int*)  d_in[1];
    const float* w_q    = (const float*)d_in[2];
    const float* w_kv_a = (const float*)d_in[3];
    const float* w_kv_b = (const float*)d_in[4];
    const float* w_o    = (const float*)d_in[5];
    const float* kv_ln  = (const float*)d_in[6];
    float* out = (float*)d_out;

    float *q, *kva, *ckv, *kvb, *attn;
    cudaGetSymbolAddress((void**)&q,    g_q);
    cudaGetSymbolAddress((void**)&kva,  g_kva);
    cudaGetSymbolAddress((void**)&ckv,  g_ckv);
    cudaGetSymbolAddress((void**)&kvb,  g_kvb);
    cudaGetSymbolAddress((void**)&attn, g_attn);

    __nv_bfloat16 *fqh, *fql, *fkh, *fkl, *fvh, *fvl;
    cudaGetSymbolAddress((void**)&fqh, g_fqh);
    cudaGetSymbolAddress((void**)&fql, g_fql);
    cudaGetSymbolAddress((void**)&fkh, g_fkh);
    cudaGetSymbolAddress((void**)&fkl, g_fkl);
    cudaGetSymbolAddress((void**)&fvh, g_fvh);
    cudaGetSymbolAddress((void**)&fvl, g_fvl);

    __nv_bfloat16 *ah, *al, *ckvh, *ckvl, *bqh, *bql, *bkah, *bkal, *bkbh, *bkbl, *boh, *bol;
    cudaGetSymbolAddress((void**)&ah,   g_ah);
    cudaGetSymbolAddress((void**)&al,   g_al);
    cudaGetSymbolAddress((void**)&ckvh, g_ckvh);
    cudaGetSymbolAddress((void**)&ckvl, g_ckvl);
    cudaGetSymbolAddress((void**)&bqh,  g_bqh);
    cudaGetSymbolAddress((void**)&bql,  g_bql);
    cudaGetSymbolAddress((void**)&bkah, g_bkah);
    cudaGetSymbolAddress((void**)&bkal, g_bkal);
    cudaGetSymbolAddress((void**)&bkbh, g_bkbh);
    cudaGetSymbolAddress((void**)&bkbl, g_bkbl);
    cudaGetSymbolAddress((void**)&boh,  g_boh);
    cudaGetSymbolAddress((void**)&bol,  g_bol);

    cudaFuncSetAttribute(hgemm, cudaFuncAttributeMaxDynamicSharedMemorySize, HG_SMEM);
    cudaFuncSetAttribute(flash_mma, cudaFuncAttributeMaxDynamicSharedMemorySize, FA_SMEM);

    // weight conversions (transpose+split):  X[K,N] -> Bt[N,K]
    split_T<<<dim3(HH*DD/32, HID/32),   256>>>(w_q,    bqh,  bql,  HID,  HH*DD);
    split_T<<<dim3(KVA_N/32, HID/32),   256>>>(w_kv_a, bkah, bkal, HID,  KVA_N);
    split_T<<<dim3(HH*2*DD/32, RANK/32),256>>>(w_kv_b, bkbh, bkbl, RANK, HH*2*DD);
    split_T<<<dim3(HID/32, HH*DD/32),   256>>>(w_o,    boh,  bol,  HH*DD, HID);
    // hidden split
    split_rows<<<(BS*HID/4 + 255)/256, 256>>>(hidden, ah, al, BS*HID/4);

    // 1. q = hidden @ w_q
    hgemm<<<dim3((HH*DD)/128, BS/128), 256, HG_SMEM>>>(ah, al, bqh, bql, q, BS, HH*DD, HID);
    // 2. kv_a = hidden @ w_kv_a
    hgemm<<<dim3(KVA_N/128, BS/128), 256, HG_SMEM>>>(ah, al, bkah, bkal, kva, BS, KVA_N, HID);
    // 3. RMSNorm
    rmsnorm_k<<<BS, 256>>>(kva, kv_ln, ckv);
    // 4. kv = c_kv @ w_kv_b
    split_rows<<<(BS*RANK/4 + 255)/256, 256>>>(ckv, ckvh, ckvl, BS*RANK/4);
    hgemm<<<dim3((HH*2*DD)/128, BS/128), 256, HG_SMEM>>>(ckvh, ckvl, bkbh, bkbl, kvb,
                                                         BS, HH*2*DD, RANK);
    // 5. RoPE + assemble (bf16 hi/lo, q pre-scaled)
    rope_combine<<<BS, 256>>>(q, kva, kvb, pos, fqh, fql, fkh, fkl, fvh, fvl);
    // 6. tensor-core flash attention
    flash_mma<<<dim3(SS/64, BB*HH), 128, FA_SMEM>>>(fqh, fql, fkh, fkl, fvh, fvl, attn);
    // 7. out = attn @ w_o
    split_rows<<<(BS*(HH*DD)/4 + 255)/256, 256>>>(attn, ah, al, BS*(HH*DD)/4);
    hgemm<<<dim3(HID/128, BS/128), 256, HG_SMEM>>>(ah, al, boh, bol, out, BS, HID, HH*DD);
}

// round 10
// speedup vs baseline: 3.0445x; 1.3774x over previous
#include <cuda_runtime.h>
#include <cuda_bf16.h>
#include <cuda_fp16.h>
#include <math.h>
#include <stdint.h>

// Problem constants
#define BB 2
#define SS 2048
#define HID 2048
#define HH 16
#define DD 128
#define RANK 512
#define BS (BB*SS)          // 4096
#define KVA_N (RANK + DD)   // 640
#define MSCALE 1.2772588722239782f
#define ATT_SCALE 0.08838834764831845f  // 1/sqrt(128)

// ---------------- scratch (device globals; no allocation allowed) -------------
__device__ float g_q[BS * (HH*DD)];
__device__ float g_kva[BS * KVA_N];
__device__ float g_kvb[BS * (HH*2*DD)];

// bf16 q/k/v hi/lo for tensor-core flash attention  [B,H,S,D]
#define QKV_ELEMS (BB*HH*SS*DD)
__device__ __nv_bfloat16 g_fqh[QKV_ELEMS], g_fql[QKV_ELEMS];
__device__ __nv_bfloat16 g_fkh[QKV_ELEMS], g_fkl[QKV_ELEMS];
__device__ __nv_bfloat16 g_fvh[QKV_ELEMS], g_fvl[QKV_ELEMS];

// fp16 split activations (hi/lo). g_ah/g_al reused: hidden first, then attn-out.
__device__ __half g_ah[BS*HID],  g_al[BS*HID];
__device__ __half g_ckvh[BS*RANK], g_ckvl[BS*RANK];
// fp16 single weights, pre-transposed to [N,K]
__device__ __half g_bq[HID*HH*DD];
__device__ __half g_bka[KVA_N*HID];
__device__ __half g_bkb[HH*2*DD*RANK];
__device__ __half g_bo[HID*HH*DD];

// =================== base-ISA helpers (compile for plain sm_103) ==============
__device__ __forceinline__ uint32_t smem_u32(const void* p) {
    uint32_t a;
    asm("{ .reg .u64 t; cvta.to.shared.u64 t, %1; cvt.u32.u64 %0, t; }"
        : "=r"(a) : "l"(p));
    return a;
}

#define CP_ASYNC16(dst, src) \
    asm volatile("cp.async.cg.shared.global [%0], [%1], 16;" :: "r"(dst), "l"(src))
#define CP_COMMIT() asm volatile("cp.async.commit_group;" ::: "memory")
#define CP_WAIT(n)  asm volatile("cp.async.wait_group %0;" :: "n"(n) : "memory")

__device__ __forceinline__ void ldm_x4(uint32_t a, uint32_t& r0, uint32_t& r1,
                                       uint32_t& r2, uint32_t& r3) {
    asm volatile("ldmatrix.sync.aligned.m8n8.x4.shared.b16 {%0,%1,%2,%3}, [%4];"
                 : "=r"(r0), "=r"(r1), "=r"(r2), "=r"(r3) : "r"(a));
}
__device__ __forceinline__ void ldm_x4t(uint32_t a, uint32_t& r0, uint32_t& r1,
                                        uint32_t& r2, uint32_t& r3) {
    asm volatile("ldmatrix.sync.aligned.m8n8.x4.trans.shared.b16 {%0,%1,%2,%3}, [%4];"
                 : "=r"(r0), "=r"(r1), "=r"(r2), "=r"(r3) : "r"(a));
}

__device__ __forceinline__ void mma_bf16(float* d, const uint32_t* a, const uint32_t* b) {
    asm volatile(
        "mma.sync.aligned.m16n8k16.row.col.f32.bf16.bf16.f32 "
        "{%0,%1,%2,%3}, {%4,%5,%6,%7}, {%8,%9}, {%0,%1,%2,%3};"
        : "+f"(d[0]), "+f"(d[1]), "+f"(d[2]), "+f"(d[3])
        : "r"(a[0]), "r"(a[1]), "r"(a[2]), "r"(a[3]), "r"(b[0]), "r"(b[1]));
}
__device__ __forceinline__ void mma_f16(float* d, const uint32_t* a, const uint32_t* b) {
    asm volatile(
        "mma.sync.aligned.m16n8k16.row.col.f32.f16.f16.f32 "
        "{%0,%1,%2,%3}, {%4,%5,%6,%7}, {%8,%9}, {%0,%1,%2,%3};"
        : "+f"(d[0]), "+f"(d[1]), "+f"(d[2]), "+f"(d[3])
        : "r"(a[0]), "r"(a[1]), "r"(a[2]), "r"(a[3]), "r"(b[0]), "r"(b[1]));
}

__device__ __forceinline__ uint32_t pack_bf16(float lo, float hi) {
    __nv_bfloat162 t = __floats2bfloat162_rn(lo, hi);
    return *reinterpret_cast<uint32_t*>(&t);
}

// =================== 2-term fp16 tensor GEMM (mma.sync) =======================
// C[M,N] = (Ah+Al)[M,K] @ B^T,  B stored [N,K] row-major fp16 single.
// CTA 128x128, 8 warps (2x4 -> 64x32 each), BK=32, cp.async double buffer.
// Stage layout: op(Ah=0,Al=1,B=2)*12288 + kb*6144 + row*48 + par*16
#define KB_BYTES    6144
#define OP_BYTES    12288
#define STAGE_BYTES 36864
#define HG_SMEM     (2*STAGE_BYTES)    // 73728

__global__ __launch_bounds__(256, 2) void hgemm(const __half* __restrict__ Ah,
                                                const __half* __restrict__ Al,
                                                const __half* __restrict__ B,
                                                float* __restrict__ C,
                                                int M, int N, int K)
{
    extern __shared__ char sm[];
    const uint32_t sb = smem_u32(sm);
    const int tid = threadIdx.x;
    const int wid = tid >> 5, lane = tid & 31;
    const int wm = wid >> 2, wn = wid & 3;
    const int bx = blockIdx.x, by = blockIdx.y;

    const int r = lane & 7, grp = lane >> 3;
    const int a_row_off = ((grp & 1) << 3) + r;
    const int a_par     = grp >> 1;
    const int b_row_off = ((grp >> 1) << 3) + r;
    const int b_par     = grp & 1;

    const __half* srcs[3] = {
        Ah + (size_t)by*128*K, Al + (size_t)by*128*K, B + (size_t)bx*128*K };

    float acc[4][4][4];
#pragma unroll
    for (int mt = 0; mt < 4; mt++)
#pragma unroll
        for (int nt = 0; nt < 4; nt++)
#pragma unroll
            for (int e = 0; e < 4; e++) acc[mt][nt][e] = 0.f;

    auto issue = [&](int c, int st) {
#pragma unroll
        for (int i = 0; i < 6; i++) {
            const int op  = i >> 1;
            const int idx = tid + (i & 1)*256;
            const int row = idx >> 2, j = idx & 3;
            const __half* s = srcs[op] + (size_t)row*K + c*32 + j*8;
            const uint32_t d = sb + st*STAGE_BYTES + op*OP_BYTES
                             + (j >> 1)*KB_BYTES + row*48 + (j & 1)*16;
            CP_ASYNC16(d, s);
        }
        CP_COMMIT();
    };

    const int NC = K >> 5;
    issue(0, 0);

    for (int c = 0; c < NC; c++) {
        const int st = c & 1;
        if (c + 1 < NC) { issue(c + 1, st ^ 1); CP_WAIT(1); }
        else            { CP_WAIT(0); }
        __syncthreads();

        const uint32_t sst = sb + st*STAGE_BYTES;
#pragma unroll
        for (int kb = 0; kb < 2; kb++) {
            uint32_t Bf[4][2];
#pragma unroll
            for (int np = 0; np < 2; np++) {
                const uint32_t ba = sst + 2*OP_BYTES + kb*KB_BYTES
                                  + (wn*32 + np*16 + b_row_off)*48 + b_par*16;
                ldm_x4(ba, Bf[np*2][0], Bf[np*2][1], Bf[np*2+1][0], Bf[np*2+1][1]);
            }
#pragma unroll
            for (int mt = 0; mt < 4; mt++) {
                const uint32_t aa = sst + kb*KB_BYTES
                                  + (wm*64 + mt*16 + a_row_off)*48 + a_par*16;
                uint32_t Afh[4], Afl[4];
                ldm_x4(aa, Afh[0], Afh[1], Afh[2], Afh[3]);
                ldm_x4(aa + OP_BYTES, Afl[0], Afl[1], Afl[2], Afl[3]);
#pragma unroll
                for (int nt = 0; nt < 4; nt++) {
                    mma_f16(acc[mt][nt], Afh, Bf[nt]);
                    mma_f16(acc[mt][nt], Afl, Bf[nt]);
                }
            }
        }
        __syncthreads();
    }

    const int tq = lane >> 2, tr = lane & 3;
#pragma unroll
    for (int mt = 0; mt < 4; mt++) {
#pragma unroll
        for (int nt = 0; nt < 4; nt++) {
            const int m0 = by*128 + wm*64 + mt*16 + tq;
            const int n0 = bx*128 + wn*32 + nt*8 + tr*2;
            float2 v0 = make_float2(acc[mt][nt][0], acc[mt][nt][1]);
            float2 v1 = make_float2(acc[mt][nt][2], acc[mt][nt][3]);
            *(float2*)(C + (size_t)m0*N + n0)       = v0;
            *(float2*)(C + (size_t)(m0+8)*N + n0)   = v1;
        }
    }
}

// =================== fp16 split conversions ====================================
__global__ __launch_bounds__(256) void split_rows_h(const float* __restrict__ X,
                                                    __half* __restrict__ H,
                                                    __half* __restrict__ L,
                                                    int n4)
{
    const int i = blockIdx.x*256 + threadIdx.x;
    if (i >= n4) return;
    float4 v = ((const float4*)X)[i];
    __half h0 = __float2half(v.x), h1 = __float2half(v.y);
    __half h2 = __float2half(v.z), h3 = __float2half(v.w);
    __half l0 = __float2half(v.x - __half2float(h0));
    __half l1 = __float2half(v.y - __half2float(h1));
    __half l2 = __float2half(v.z - __half2float(h2));
    __half l3 = __float2half(v.w - __half2float(h3));
    ((__half2*)H)[i*2+0] = __halves2half2(h0, h1);
    ((__half2*)H)[i*2+1] = __halves2half2(h2, h3);
    ((__half2*)L)[i*2+0] = __halves2half2(l0, l1);
    ((__half2*)L)[i*2+1] = __halves2half2(l2, l3);
}

// transpose to fp16 single: X[Kd,Nd] fp32 -> H fp16 [Nd,Kd]
__global__ __launch_bounds__(256) void split_T1(const float* __restrict__ X,
                                                __half* __restrict__ H,
                                                int Kd, int Nd)
{
    __shared__ float t[32][33];
    const int tx = threadIdx.x & 31, ty = threadIdx.x >> 5;
    const int c0 = blockIdx.x*32, r0 = blockIdx.y*32;
#pragma unroll
    for (int i = 0; i < 4; i++)
        t[ty + i*8][tx] = X[(size_t)(r0 + ty + i*8)*Nd + c0 + tx];
    __syncthreads();
#pragma unroll
    for (int i = 0; i < 4; i++) {
        const float x = t[tx][ty + i*8];
        H[(size_t)(c0 + ty + i*8)*Kd + r0 + tx] = __float2half(x);
    }
}

// ------- RMSNorm over first 512 cols of kv_a, fused fp16 hi/lo split ----------
__global__ __launch_bounds__(256) void rmsnorm_k(const float* __restrict__ kva,
                                                 const float* __restrict__ w,
                                                 __half* __restrict__ outh,
                                                 __half* __restrict__ outl)
{
    const int row = blockIdx.x;
    const float* x = kva + (size_t)row * KVA_N;
    float s = 0.f;
    for (int i = threadIdx.x; i < RANK; i += 256) { float v = x[i]; s = fmaf(v, v, s); }
#pragma unroll
    for (int o = 16; o; o >>= 1) s += __shfl_xor_sync(0xffffffffu, s, o);
    __shared__ float red[8];
    __shared__ float inv_s;
    if ((threadIdx.x & 31) == 0) red[threadIdx.x >> 5] = s;
    __syncthreads();
    if (threadIdx.x == 0) {
        float t = 0.f;
#pragma unroll
        for (int i = 0; i < 8; i++) t += red[i];
        inv_s = rsqrtf(t * (1.f/512.f) + 1e-6f);
    }
    __syncthreads();
    const float inv = inv_s;
    for (int i = threadIdx.x; i < RANK; i += 256) {
        const float v = w[i] * (x[i] * inv);
        const __half h = __float2half(v);
        outh[(size_t)row * RANK + i] = h;
        outl[(size_t)row * RANK + i] = __float2half(v - __half2float(h));
    }
}

// ------- YaRN RoPE + k/v assembly; emits bf16 hi/lo (q pre-scaled) ------------
__global__ __launch_bounds__(256) void rope_combine(const float* __restrict__ qpre,
                                                    const float* __restrict__ kva,
                                                    const float* __restrict__ kvb,
                                                    const int*   __restrict__ pos_ids,
                                                    __nv_bfloat16* __restrict__ qh,
                                                    __nv_bfloat16* __restrict__ ql,
                                                    __nv_bfloat16* __restrict__ kh,
                                                    __nv_bfloat16* __restrict__ kl,
                                                    __nv_bfloat16* __restrict__ vh,
                                                    __nv_bfloat16* __restrict__ vl)
{
    const int row = blockIdx.x;
    const int b = row >> 11;
    const int s = row & 2047;
    const int tid = threadIdx.x;

    __shared__ float cs[128], sn[128], krot[128];
    const float pos = (float)pos_ids[row];

    if (tid < 128) {
        const int j = tid & 63;
        const float fj = (float)j;
        const float extrap = expf(-fj * 0.015625f * 13.122363377404328f);
        float smooth = (fj - 18.f) * (1.f / 17.f);
        smooth = fminf(fmaxf(smooth, 0.f), 1.f);
        const float invf = extrap * ((1.f - smooth) * 0.0625f + smooth);
        const float fr = pos * invf;
        cs[tid] = cosf(fr) * MSCALE;
        sn[tid] = sinf(fr) * MSCALE;
        krot[tid] = kva[(size_t)row * KVA_N + RANK + tid];
    }
    __syncthreads();
    float kv_ = 0.f;
    if (tid < 128) {
        const int d = tid;
        const float x = krot[d];
        const float pr = (d < 64) ? -krot[d + 64] : krot[d - 64];
        kv_ = fmaf(x, cs[d], pr * sn[d]);
    }
    __syncthreads();
    if (tid < 128) krot[tid] = kv_;
    __syncthreads();

    for (int e = tid; e < HH*DD; e += 256) {
        const int h = e >> 7, d = e & 127;
        const float x  = qpre[(size_t)row * (HH*DD) + e];
        const float pr = qpre[(size_t)row * (HH*DD) + h*128 + ((d < 64) ? d + 64 : d - 64)];
        const float qv = (d < 64) ? fmaf(x, cs[d], -pr * sn[d])
                                  : fmaf(x, cs[d],  pr * sn[d]);
        const float kvv = kvb[(size_t)row * (HH*2*DD) + h*256 + d] + krot[d];
        const float vvv = kvb[(size_t)row * (HH*2*DD) + h*256 + 128 + d];
        const size_t oidx = (((size_t)(b*HH + h)) * SS + s) * DD + d;

        const float qs = qv * ATT_SCALE;
        __nv_bfloat16 a = __float2bfloat16(qs);
        qh[oidx] = a; ql[oidx] = __float2bfloat16(qs - __bfloat162float(a));
        a = __float2bfloat16(kvv);
        kh[oidx] = a; kl[oidx] = __float2bfloat16(kvv - __bfloat162float(a));
        a = __float2bfloat16(vvv);
        vh[oidx] = a; vl[oidx] = __float2bfloat16(vvv - __bfloat162float(a));
    }
}

// ---------------- tensor-core flash attention (split-bf16, causal) ------------
// BM=64 (4 warps x m16), BN=64, D=128. 272B-padded smem rows.
// Epilogue writes fp16 hi/lo directly for the o-proj GEMM.
#define FA_STRIDE 272
#define FA_TILE   (64*FA_STRIDE)       // 17408
#define FA_SMEM   (10*FA_TILE)

__global__ __launch_bounds__(128) void flash_mma(const __nv_bfloat16* __restrict__ Qh_,
                                                 const __nv_bfloat16* __restrict__ Ql_,
                                                 const __nv_bfloat16* __restrict__ Kh_,
                                                 const __nv_bfloat16* __restrict__ Kl_,
                                                 const __nv_bfloat16* __restrict__ Vh_,
                                                 const __nv_bfloat16* __restrict__ Vl_,
                                                 __half* __restrict__ Oh,
                                                 __half* __restrict__ Ol)
{
    const int mt = blockIdx.x;
    const int bh = blockIdx.y;
    const int b = bh >> 4, h = bh & 15;
    const int tid = threadIdx.x;
    const int wid = tid >> 5, lane = tid & 31;
    const int grp = lane >> 3, r8 = lane & 7;
    const int tq = lane >> 2, tr = lane & 3;

    extern __shared__ char smc[];
    const uint32_t sb  = smem_u32(smc);
    const uint32_t sQh = sb, sQl = sb + FA_TILE;

    const size_t qoff = ((size_t)bh*SS + (size_t)mt*64)*DD;
    {
        const __nv_bfloat16* s0 = Qh_ + qoff;
        const __nv_bfloat16* s1 = Ql_ + qoff;
#pragma unroll
        for (int i = 0; i < 8; i++) {
            const int idx = tid + i*128;
            const int row = idx >> 4, ch = idx & 15;
            CP_ASYNC16(sQh + row*FA_STRIDE + ch*16, s0 + row*128 + ch*8);
            CP_ASYNC16(sQl + row*FA_STRIDE + ch*16, s1 + row*128 + ch*8);
        }
        CP_COMMIT();
    }

    auto issueKV = [&](int nt, int st) {
        const size_t koff = ((size_t)bh*SS + (size_t)nt*64)*DD;
        const __nv_bfloat16* srcs[4] = {Kh_+koff, Kl_+koff, Vh_+koff, Vl_+koff};
        const uint32_t base = sb + 2*FA_TILE + st*4*FA_TILE;
#pragma unroll
        for (int t4 = 0; t4 < 4; t4++) {
            const uint32_t dt = base + t4*FA_TILE;
            const __nv_bfloat16* s = srcs[t4];
#pragma unroll
            for (int i = 0; i < 8; i++) {
                const int idx = tid + i*128;
                const int row = idx >> 4, ch = idx & 15;
                CP_ASYNC16(dt + row*FA_STRIDE + ch*16, s + row*128 + ch*8);
            }
        }
        CP_COMMIT();
    };

    float o[16][4];
#pragma unroll
    for (int j = 0; j < 16; j++)
#pragma unroll
        for (int e = 0; e < 4; e++) o[j][e] = 0.f;
    float mrow0 = -1e30f, mrow1 = -1e30f, se0 = 0.f, se1 = 0.f;

    const uint32_t a_row   = wid*16 + ((grp & 1) << 3) + r8;
    const uint32_t a_par   = (grp >> 1);
    const uint32_t b_row   = ((grp >> 1) << 3) + r8;
    const uint32_t b_par   = (grp & 1);
    const uint32_t v_krow  = ((grp & 1) << 3) + r8;
    const uint32_t v_ncol  = ((grp >> 1) << 3);

    issueKV(0, 0);

    for (int nt = 0; nt <= mt; nt++) {
        const int st = nt & 1;
        __syncthreads();
        if (nt < mt) { issueKV(nt + 1, st ^ 1); CP_WAIT(1); }
        else         { CP_WAIT(0); }
        __syncthreads();

        const uint32_t sKh = sb + 2*FA_TILE + st*4*FA_TILE;
        const uint32_t sKl = sKh + FA_TILE;
        const uint32_t sVh = sKl + FA_TILE;
        const uint32_t sVl = sVh + FA_TILE;

        float s[8][4];
#pragma unroll
        for (int j = 0; j < 8; j++)
#pragma unroll
            for (int e = 0; e < 4; e++) s[j][e] = 0.f;

#pragma unroll
        for (int k = 0; k < 8; k++) {
            uint32_t qfh[4], qfl[4];
            const uint32_t qa = sQh + a_row*FA_STRIDE + k*32 + a_par*16;
            ldm_x4(qa, qfh[0], qfh[1], qfh[2], qfh[3]);
            ldm_x4(qa + FA_TILE, qfl[0], qfl[1], qfl[2], qfl[3]);
#pragma unroll
            for (int p = 0; p < 4; p++) {
                uint32_t kfh[2][2], kfl[2][2];
                const uint32_t ka = sKh + (p*16 + b_row)*FA_STRIDE + k*32 + b_par*16;
                ldm_x4(ka, kfh[0][0], kfh[0][1], kfh[1][0], kfh[1][1]);
                ldm_x4(ka + FA_TILE, kfl[0][0], kfl[0][1], kfl[1][0], kfl[1][1]);
                mma_bf16(s[2*p],   qfh, kfh[0]);
                mma_bf16(s[2*p],   qfh, kfl[0]);
                mma_bf16(s[2*p],   qfl, kfh[0]);
                mma_bf16(s[2*p+1], qfh, kfh[1]);
                mma_bf16(s[2*p+1], qfh, kfl[1]);
                mma_bf16(s[2*p+1], qfl, kfh[1]);
            }
        }

        if (nt == mt) {
            const int gi0 = mt*64 + wid*16 + tq;
            const int gi1 = gi0 + 8;
#pragma unroll
            for (int j = 0; j < 8; j++) {
                const int gj0 = nt*64 + j*8 + tr*2;
                if (gj0     > gi0) s[j][0] = -1e30f;
                if (gj0 + 1 > gi0) s[j][1] = -1e30f;
                if (gj0     > gi1) s[j][2] = -1e30f;
                if (gj0 + 1 > gi1) s[j][3] = -1e30f;
            }
        }

        float mx0 = -1e30f, mx1 = -1e30f;
#pragma unroll
        for (int j = 0; j < 8; j++) {
            mx0 = fmaxf(mx0, fmaxf(s[j][0], s[j][1]));
            mx1 = fmaxf(mx1, fmaxf(s[j][2], s[j][3]));
        }
        mx0 = fmaxf(mx0, __shfl_xor_sync(0xffffffffu, mx0, 1));
        mx0 = fmaxf(mx0, __shfl_xor_sync(0xffffffffu, mx0, 2));
        mx1 = fmaxf(mx1, __shfl_xor_sync(0xffffffffu, mx1, 1));
        mx1 = fmaxf(mx1, __shfl_xor_sync(0xffffffffu, mx1, 2));
        const float nm0 = fmaxf(mrow0, mx0);
        const float nm1 = fmaxf(mrow1, mx1);
        const float c0 = expf(mrow0 - nm0);
        const float c1 = expf(mrow1 - nm1);
        float sum0 = 0.f, sum1 = 0.f;
#pragma unroll
        for (int j = 0; j < 8; j++) {
            s[j][0] = expf(s[j][0] - nm0); sum0 += s[j][0];
            s[j][1] = expf(s[j][1] - nm0); sum0 += s[j][1];
            s[j][2] = expf(s[j][2] - nm1); sum1 += s[j][2];
            s[j][3] = expf(s[j][3] - nm1); sum1 += s[j][3];
        }
        sum0 += __shfl_xor_sync(0xffffffffu, sum0, 1);
        sum0 += __shfl_xor_sync(0xffffffffu, sum0, 2);
        sum1 += __shfl_xor_sync(0xffffffffu, sum1, 1);
        sum1 += __shfl_xor_sync(0xffffffffu, sum1, 2);
        se0 = se0 * c0 + sum0;
        se1 = se1 * c1 + sum1;
        mrow0 = nm0; mrow1 = nm1;
#pragma unroll
        for (int j = 0; j < 16; j++) {
            o[j][0] *= c0; o[j][1] *= c0;
            o[j][2] *= c1; o[j][3] *= c1;
        }

        uint32_t ph[4][4], pl[4][4];
#pragma unroll
        for (int t = 0; t < 4; t++) {
#pragma unroll
            for (int hf = 0; hf < 2; hf++) {
                const int tile = 2*t + hf;
                const float p0 = s[tile][0], p1 = s[tile][1];
                const float p2 = s[tile][2], p3 = s[tile][3];
                const __nv_bfloat16 h0 = __float2bfloat16(p0);
                const __nv_bfloat16 h1 = __float2bfloat16(p1);
                const __nv_bfloat16 h2 = __float2bfloat16(p2);
                const __nv_bfloat16 h3 = __float2bfloat16(p3);
                ph[t][2*hf+0] = pack_bf16(__bfloat162float(h0), __bfloat162float(h1));
                ph[t][2*hf+1] = pack_bf16(__bfloat162float(h2), __bfloat162float(h3));
                pl[t][2*hf+0] = pack_bf16(p0 - __bfloat162float(h0),
                                          p1 - __bfloat162float(h1));
                pl[t][2*hf+1] = pack_bf16(p2 - __bfloat162float(h2),
                                          p3 - __bfloat162float(h3));
            }
        }

#pragma unroll
        for (int t = 0; t < 4; t++) {
#pragma unroll
            for (int p = 0; p < 8; p++) {
                uint32_t vfh[2][2], vfl[2][2];
                const uint32_t va = sVh + (t*16 + v_krow)*FA_STRIDE
                                  + (p*16 + v_ncol)*2;
                ldm_x4t(va, vfh[0][0], vfh[0][1], vfh[1][0], vfh[1][1]);
                ldm_x4t(va + FA_TILE, vfl[0][0], vfl[0][1], vfl[1][0], vfl[1][1]);
                mma_bf16(o[2*p],   ph[t], vfh[0]);
                mma_bf16(o[2*p],   ph[t], vfl[0]);
                mma_bf16(o[2*p],   pl[t], vfh[0]);
                mma_bf16(o[2*p+1], ph[t], vfh[1]);
                mma_bf16(o[2*p+1], ph[t], vfl[1]);
                mma_bf16(o[2*p+1], pl[t], vfh[1]);
            }
        }
    }

    // ---- epilogue: write fp16 hi/lo for o-proj GEMM ----
    const float i0 = 1.f / (se0 + 1e-5f);
    const float i1 = 1.f / (se1 + 1e-5f);
    const int s0 = mt*64 + wid*16 + tq;
    const size_t off0 = ((size_t)(b*SS + s0))*(HH*DD) + h*DD;
    const size_t off1 = off0 + (size_t)8*(HH*DD);
#pragma unroll
    for (int j = 0; j < 16; j++) {
        const int col = j*8 + tr*2;
        const float v0 = o[j][0]*i0, v1 = o[j][1]*i0;
        const float v2 = o[j][2]*i1, v3 = o[j][3]*i1;
        const __half h0 = __float2half(v0), h1 = __float2half(v1);
        const __half h2 = __float2half(v2), h3 = __float2half(v3);
        *(__half2*)(Oh + off0 + col) = __halves2half2(h0, h1);
        *(__half2*)(Oh + off1 + col) = __halves2half2(h2, h3);
        *(__half2*)(Ol + off0 + col) =
            __halves2half2(__float2half(v0 - __half2float(h0)),
                           __float2half(v1 - __half2float(h1)));
        *(__half2*)(Ol + off1 + col) =
            __halves2half2(__float2half(v2 - __half2float(h2)),
                           __float2half(v3 - __half2float(h3)));
    }
}

// ---------------- launch --------------------------------------------------------
extern "C" void kernel_launch(void* const* d_in, const int* in_sizes, int n_in,
                              void* d_out, int out_size)
{
    const float* hidden = (const float*)d_in[0];
    const int*   pos    = (const int*)  d_in[1];
    const float* w_q    = (const float*)d_in[2];
    const float* w_kv_a = (const float*)d_in[3];
    const float* w_kv_b = (const float*)d_in[4];
    const float* w_o    = (const float*)d_in[5];
    const float* kv_ln  = (const float*)d_in[6];
    float* out = (float*)d_out;

    float *q, *kva, *kvb;
    cudaGetSymbolAddress((void**)&q,    g_q);
    cudaGetSymbolAddress((void**)&kva,  g_kva);
    cudaGetSymbolAddress((void**)&kvb,  g_kvb);

    __nv_bfloat16 *fqh, *fql, *fkh, *fkl, *fvh, *fvl;
    cudaGetSymbolAddress((void**)&fqh, g_fqh);
    cudaGetSymbolAddress((void**)&fql, g_fql);
    cudaGetSymbolAddress((void**)&fkh, g_fkh);
    cudaGetSymbolAddress((void**)&fkl, g_fkl);
    cudaGetSymbolAddress((void**)&fvh, g_fvh);
    cudaGetSymbolAddress((void**)&fvl, g_fvl);

    __half *ah, *al, *ckvh, *ckvl, *bq, *bka, *bkb, *bo;
    cudaGetSymbolAddress((void**)&ah,   g_ah);
    cudaGetSymbolAddress((void**)&al,   g_al);
    cudaGetSymbolAddress((void**)&ckvh, g_ckvh);
    cudaGetSymbolAddress((void**)&ckvl, g_ckvl);
    cudaGetSymbolAddress((void**)&bq,   g_bq);
    cudaGetSymbolAddress((void**)&bka,  g_bka);
    cudaGetSymbolAddress((void**)&bkb,  g_bkb);
    cudaGetSymbolAddress((void**)&bo,   g_bo);

    cudaFuncSetAttribute(hgemm, cudaFuncAttributeMaxDynamicSharedMemorySize, HG_SMEM);
    cudaFuncSetAttribute(flash_mma, cudaFuncAttributeMaxDynamicSharedMemorySize, FA_SMEM);

    // weight conversions (transpose, fp16 single):  X[K,N] -> Bt[N,K]
    split_T1<<<dim3(HH*DD/32, HID/32),   256>>>(w_q,    bq,  HID,  HH*DD);
    split_T1<<<dim3(KVA_N/32, HID/32),   256>>>(w_kv_a, bka, HID,  KVA_N);
    split_T1<<<dim3(HH*2*DD/32, RANK/32),256>>>(w_kv_b, bkb, RANK, HH*2*DD);
    split_T1<<<dim3(HID/32, HH*DD/32),   256>>>(w_o,    bo,  HH*DD, HID);
    // hidden split (fp16 hi/lo)
    split_rows_h<<<(BS*HID/4 + 255)/256, 256>>>(hidden, ah, al, BS*HID/4);

    // 1. q = hidden @ w_q
    hgemm<<<dim3((HH*DD)/128, BS/128), 256, HG_SMEM>>>(ah, al, bq, q, BS, HH*DD, HID);
    // 2. kv_a = hidden @ w_kv_a
    hgemm<<<dim3(KVA_N/128, BS/128), 256, HG_SMEM>>>(ah, al, bka, kva, BS, KVA_N, HID);
    // 3. RMSNorm (fused fp16 split)
    rmsnorm_k<<<BS, 256>>>(kva, kv_ln, ckvh, ckvl);
    // 4. kv = c_kv @ w_kv_b
    hgemm<<<dim3((HH*2*DD)/128, BS/128), 256, HG_SMEM>>>(ckvh, ckvl, bkb, kvb,
                                                         BS, HH*2*DD, RANK);
    // 5. RoPE + assemble (bf16 hi/lo, q pre-scaled)
    rope_combine<<<BS, 256>>>(q, kva, kvb, pos, fqh, fql, fkh, fkl, fvh, fvl);
    // 6. tensor-core flash attention (writes fp16 hi/lo into ah/al)
    flash_mma<<<dim3(SS/64, BB*HH), 128, FA_SMEM>>>(fqh, fql, fkh, fkl, fvh, fvl, ah, al);
    // 7. out = attn @ w_o
    hgemm<<<dim3(HID/128, BS/128), 256, HG_SMEM>>>(ah, al, bo, out, BS, HID, HH*DD);
}

// round 11
// speedup vs baseline: 3.8361x; 1.2600x over previous
#include <cuda_runtime.h>
#include <cuda_bf16.h>
#include <cuda_fp16.h>
#include <math.h>
#include <stdint.h>

// Problem constants
#define BB 2
#define SS 2048
#define HID 2048
#define HH 16
#define DD 128
#define RANK 512
#define BS (BB*SS)          // 4096
#define KVA_N (RANK + DD)   // 640
#define MSCALE 1.2772588722239782f
#define ATT_SCALE 0.08838834764831845f  // 1/sqrt(128)

// ---------------- scratch (device globals; no allocation allowed) -------------
__device__ float g_q[BS * (HH*DD)];
__device__ float g_kva[BS * KVA_N];
__device__ float g_kvb[BS * (HH*2*DD)];

// fp16 q (hi/lo) and k/v (single) for tensor-core flash attention  [B,H,S,D]
#define QKV_ELEMS (BB*HH*SS*DD)
__device__ __half g_fqh[QKV_ELEMS], g_fql[QKV_ELEMS];
__device__ __half g_fk[QKV_ELEMS];
__device__ __half g_fv[QKV_ELEMS];

// fp16 split activations (hi/lo). g_ah/g_al reused: hidden first, then attn-out.
__device__ __half g_ah[BS*HID],  g_al[BS*HID];
__device__ __half g_ckvh[BS*RANK], g_ckvl[BS*RANK];
// fp16 single weights, pre-transposed to [N,K]
__device__ __half g_bq[HID*HH*DD];
__device__ __half g_bka[KVA_N*HID];
__device__ __half g_bkb[HH*2*DD*RANK];
__device__ __half g_bo[HID*HH*DD];

// =================== base-ISA helpers (compile for plain sm_103) ==============
__device__ __forceinline__ uint32_t smem_u32(const void* p) {
    uint32_t a;
    asm("{ .reg .u64 t; cvta.to.shared.u64 t, %1; cvt.u32.u64 %0, t; }"
        : "=r"(a) : "l"(p));
    return a;
}

#define CP_ASYNC16(dst, src) \
    asm volatile("cp.async.cg.shared.global [%0], [%1], 16;" :: "r"(dst), "l"(src))
#define CP_COMMIT() asm volatile("cp.async.commit_group;" ::: "memory")
#define CP_WAIT(n)  asm volatile("cp.async.wait_group %0;" :: "n"(n) : "memory")

__device__ __forceinline__ void ldm_x4(uint32_t a, uint32_t& r0, uint32_t& r1,
                                       uint32_t& r2, uint32_t& r3) {
    asm volatile("ldmatrix.sync.aligned.m8n8.x4.shared.b16 {%0,%1,%2,%3}, [%4];"
                 : "=r"(r0), "=r"(r1), "=r"(r2), "=r"(r3) : "r"(a));
}
__device__ __forceinline__ void ldm_x4t(uint32_t a, uint32_t& r0, uint32_t& r1,
                                        uint32_t& r2, uint32_t& r3) {
    asm volatile("ldmatrix.sync.aligned.m8n8.x4.trans.shared.b16 {%0,%1,%2,%3}, [%4];"
                 : "=r"(r0), "=r"(r1), "=r"(r2), "=r"(r3) : "r"(a));
}

__device__ __forceinline__ void mma_f16(float* d, const uint32_t* a, const uint32_t* b) {
    asm volatile(
        "mma.sync.aligned.m16n8k16.row.col.f32.f16.f16.f32 "
        "{%0,%1,%2,%3}, {%4,%5,%6,%7}, {%8,%9}, {%0,%1,%2,%3};"
        : "+f"(d[0]), "+f"(d[1]), "+f"(d[2]), "+f"(d[3])
        : "r"(a[0]), "r"(a[1]), "r"(a[2]), "r"(a[3]), "r"(b[0]), "r"(b[1]));
}

__device__ __forceinline__ uint32_t pack_f16(float lo, float hi) {
    __half2 t = __floats2half2_rn(lo, hi);
    return *reinterpret_cast<uint32_t*>(&t);
}

// =================== 2-term fp16 tensor GEMM (mma.sync) =======================
// C[M,N] = (Ah+Al)[M,K] @ B^T,  B stored [N,K] row-major fp16 single.
// CTA 128x128, 8 warps (2x4 -> 64x32 each), BK=32, cp.async double buffer.
#define KB_BYTES    6144
#define OP_BYTES    12288
#define STAGE_BYTES 36864
#define HG_SMEM     (2*STAGE_BYTES)    // 73728

__global__ __launch_bounds__(256, 2) void hgemm(const __half* __restrict__ Ah,
                                                const __half* __restrict__ Al,
                                                const __half* __restrict__ B,
                                                float* __restrict__ C,
                                                int M, int N, int K)
{
    extern __shared__ char sm[];
    const uint32_t sb = smem_u32(sm);
    const int tid = threadIdx.x;
    const int wid = tid >> 5, lane = tid & 31;
    const int wm = wid >> 2, wn = wid & 3;
    const int bx = blockIdx.x, by = blockIdx.y;

    const int r = lane & 7, grp = lane >> 3;
    const int a_row_off = ((grp & 1) << 3) + r;
    const int a_par     = grp >> 1;
    const int b_row_off = ((grp >> 1) << 3) + r;
    const int b_par     = grp & 1;

    const __half* srcs[3] = {
        Ah + (size_t)by*128*K, Al + (size_t)by*128*K, B + (size_t)bx*128*K };

    float acc[4][4][4];
#pragma unroll
    for (int mt = 0; mt < 4; mt++)
#pragma unroll
        for (int nt = 0; nt < 4; nt++)
#pragma unroll
            for (int e = 0; e < 4; e++) acc[mt][nt][e] = 0.f;

    auto issue = [&](int c, int st) {
#pragma unroll
        for (int i = 0; i < 6; i++) {
            const int op  = i >> 1;
            const int idx = tid + (i & 1)*256;
            const int row = idx >> 2, j = idx & 3;
            const __half* s = srcs[op] + (size_t)row*K + c*32 + j*8;
            const uint32_t d = sb + st*STAGE_BYTES + op*OP_BYTES
                             + (j >> 1)*KB_BYTES + row*48 + (j & 1)*16;
            CP_ASYNC16(d, s);
        }
        CP_COMMIT();
    };

    const int NC = K >> 5;
    issue(0, 0);

    for (int c = 0; c < NC; c++) {
        const int st = c & 1;
        if (c + 1 < NC) { issue(c + 1, st ^ 1); CP_WAIT(1); }
        else            { CP_WAIT(0); }
        __syncthreads();

        const uint32_t sst = sb + st*STAGE_BYTES;
#pragma unroll
        for (int kb = 0; kb < 2; kb++) {
            uint32_t Bf[4][2];
#pragma unroll
            for (int np = 0; np < 2; np++) {
                const uint32_t ba = sst + 2*OP_BYTES + kb*KB_BYTES
                                  + (wn*32 + np*16 + b_row_off)*48 + b_par*16;
                ldm_x4(ba, Bf[np*2][0], Bf[np*2][1], Bf[np*2+1][0], Bf[np*2+1][1]);
            }
#pragma unroll
            for (int mt = 0; mt < 4; mt++) {
                const uint32_t aa = sst + kb*KB_BYTES
                                  + (wm*64 + mt*16 + a_row_off)*48 + a_par*16;
                uint32_t Afh[4], Afl[4];
                ldm_x4(aa, Afh[0], Afh[1], Afh[2], Afh[3]);
                ldm_x4(aa + OP_BYTES, Afl[0], Afl[1], Afl[2], Afl[3]);
#pragma unroll
                for (int nt = 0; nt < 4; nt++) {
                    mma_f16(acc[mt][nt], Afh, Bf[nt]);
                    mma_f16(acc[mt][nt], Afl, Bf[nt]);
                }
            }
        }
        __syncthreads();
    }

    const int tq = lane >> 2, tr = lane & 3;
#pragma unroll
    for (int mt = 0; mt < 4; mt++) {
#pragma unroll
        for (int nt = 0; nt < 4; nt++) {
            const int m0 = by*128 + wm*64 + mt*16 + tq;
            const int n0 = bx*128 + wn*32 + nt*8 + tr*2;
            float2 v0 = make_float2(acc[mt][nt][0], acc[mt][nt][1]);
            float2 v1 = make_float2(acc[mt][nt][2], acc[mt][nt][3]);
            *(float2*)(C + (size_t)m0*N + n0)       = v0;
            *(float2*)(C + (size_t)(m0+8)*N + n0)   = v1;
        }
    }
}

// =================== fp16 split conversions ====================================
__global__ __launch_bounds__(256) void split_rows_h(const float* __restrict__ X,
                                                    __half* __restrict__ H,
                                                    __half* __restrict__ L,
                                                    int n4)
{
    const int i = blockIdx.x*256 + threadIdx.x;
    if (i >= n4) return;
    float4 v = ((const float4*)X)[i];
    __half h0 = __float2half(v.x), h1 = __float2half(v.y);
    __half h2 = __float2half(v.z), h3 = __float2half(v.w);
    __half l0 = __float2half(v.x - __half2float(h0));
    __half l1 = __float2half(v.y - __half2float(h1));
    __half l2 = __float2half(v.z - __half2float(h2));
    __half l3 = __float2half(v.w - __half2float(h3));
    ((__half2*)H)[i*2+0] = __halves2half2(h0, h1);
    ((__half2*)H)[i*2+1] = __halves2half2(h2, h3);
    ((__half2*)L)[i*2+0] = __halves2half2(l0, l1);
    ((__half2*)L)[i*2+1] = __halves2half2(l2, l3);
}

// transpose to fp16 single: X[Kd,Nd] fp32 -> H fp16 [Nd,Kd]
__global__ __launch_bounds__(256) void split_T1(const float* __restrict__ X,
                                                __half* __restrict__ H,
                                                int Kd, int Nd)
{
    __shared__ float t[32][33];
    const int tx = threadIdx.x & 31, ty = threadIdx.x >> 5;
    const int c0 = blockIdx.x*32, r0 = blockIdx.y*32;
#pragma unroll
    for (int i = 0; i < 4; i++)
        t[ty + i*8][tx] = X[(size_t)(r0 + ty + i*8)*Nd + c0 + tx];
    __syncthreads();
#pragma unroll
    for (int i = 0; i < 4; i++) {
        const float x = t[tx][ty + i*8];
        H[(size_t)(c0 + ty + i*8)*Kd + r0 + tx] = __float2half(x);
    }
}

// ------- RMSNorm over first 512 cols of kv_a, fused fp16 hi/lo split ----------
__global__ __launch_bounds__(256) void rmsnorm_k(const float* __restrict__ kva,
                                                 const float* __restrict__ w,
                                                 __half* __restrict__ outh,
                                                 __half* __restrict__ outl)
{
    const int row = blockIdx.x;
    const float* x = kva + (size_t)row * KVA_N;
    float s = 0.f;
    for (int i = threadIdx.x; i < RANK; i += 256) { float v = x[i]; s = fmaf(v, v, s); }
#pragma unroll
    for (int o = 16; o; o >>= 1) s += __shfl_xor_sync(0xffffffffu, s, o);
    __shared__ float red[8];
    __shared__ float inv_s;
    if ((threadIdx.x & 31) == 0) red[threadIdx.x >> 5] = s;
    __syncthreads();
    if (threadIdx.x == 0) {
        float t = 0.f;
#pragma unroll
        for (int i = 0; i < 8; i++) t += red[i];
        inv_s = rsqrtf(t * (1.f/512.f) + 1e-6f);
    }
    __syncthreads();
    const float inv = inv_s;
    for (int i = threadIdx.x; i < RANK; i += 256) {
        const float v = w[i] * (x[i] * inv);
        const __half h = __float2half(v);
        outh[(size_t)row * RANK + i] = h;
        outl[(size_t)row * RANK + i] = __float2half(v - __half2float(h));
    }
}

// ------- YaRN RoPE + k/v assembly; emits fp16 (q hi/lo pre-scaled; k/v single) -
__global__ __launch_bounds__(256) void rope_combine(const float* __restrict__ qpre,
                                                    const float* __restrict__ kva,
                                                    const float* __restrict__ kvb,
                                                    const int*   __restrict__ pos_ids,
                                                    __half* __restrict__ qh,
                                                    __half* __restrict__ ql,
                                                    __half* __restrict__ kO,
                                                    __half* __restrict__ vO)
{
    const int row = blockIdx.x;
    const int b = row >> 11;
    const int s = row & 2047;
    const int tid = threadIdx.x;

    __shared__ float cs[128], sn[128], krot[128];
    const float pos = (float)pos_ids[row];

    if (tid < 128) {
        const int j = tid & 63;
        const float fj = (float)j;
        const float extrap = expf(-fj * 0.015625f * 13.122363377404328f);
        float smooth = (fj - 18.f) * (1.f / 17.f);
        smooth = fminf(fmaxf(smooth, 0.f), 1.f);
        const float invf = extrap * ((1.f - smooth) * 0.0625f + smooth);
        const float fr = pos * invf;
        cs[tid] = cosf(fr) * MSCALE;
        sn[tid] = sinf(fr) * MSCALE;
        krot[tid] = kva[(size_t)row * KVA_N + RANK + tid];
    }
    __syncthreads();
    float kv_ = 0.f;
    if (tid < 128) {
        const int d = tid;
        const float x = krot[d];
        const float pr = (d < 64) ? -krot[d + 64] : krot[d - 64];
        kv_ = fmaf(x, cs[d], pr * sn[d]);
    }
    __syncthreads();
    if (tid < 128) krot[tid] = kv_;
    __syncthreads();

    for (int e = tid; e < HH*DD; e += 256) {
        const int h = e >> 7, d = e & 127;
        const float x  = qpre[(size_t)row * (HH*DD) + e];
        const float pr = qpre[(size_t)row * (HH*DD) + h*128 + ((d < 64) ? d + 64 : d - 64)];
        const float qv = (d < 64) ? fmaf(x, cs[d], -pr * sn[d])
                                  : fmaf(x, cs[d],  pr * sn[d]);
        const float kvv = kvb[(size_t)row * (HH*2*DD) + h*256 + d] + krot[d];
        const float vvv = kvb[(size_t)row * (HH*2*DD) + h*256 + 128 + d];
        const size_t oidx = (((size_t)(b*HH + h)) * SS + s) * DD + d;

        const float qs = qv * ATT_SCALE;
        const __half a = __float2half(qs);
        qh[oidx] = a;
        ql[oidx] = __float2half(qs - __half2float(a));
        kO[oidx] = __float2half(kvv);
        vO[oidx] = __float2half(vvv);
    }
}

// ------- tensor-core flash attention (fp16: Q 2-term, K/V/P single, causal) ----
// BM=64 (4 warps x m16), BN=64, D=128. 272B-padded smem rows.
// QK: 2 MMAs/n8-tile; PV: 1 MMA/n8-tile. KV double-buffered (K,V single tiles).
// Epilogue writes fp16 hi/lo directly for the o-proj GEMM.
#define FA_STRIDE 272
#define FA_TILE   (64*FA_STRIDE)       // 17408
#define FA_SMEM   (6*FA_TILE)          // Qh,Ql + 2 x (K,V) = 104448

__global__ __launch_bounds__(128, 2) void flash_mma(const __half* __restrict__ Qh_,
                                                    const __half* __restrict__ Ql_,
                                                    const __half* __restrict__ K_,
                                                    const __half* __restrict__ V_,
                                                    __half* __restrict__ Oh,
                                                    __half* __restrict__ Ol)
{
    const int mt = blockIdx.x;
    const int bh = blockIdx.y;
    const int b = bh >> 4, h = bh & 15;
    const int tid = threadIdx.x;
    const int wid = tid >> 5, lane = tid & 31;
    const int grp = lane >> 3, r8 = lane & 7;
    const int tq = lane >> 2, tr = lane & 3;

    extern __shared__ char smc[];
    const uint32_t sb  = smem_u32(smc);
    const uint32_t sQh = sb, sQl = sb + FA_TILE;

    const size_t qoff = ((size_t)bh*SS + (size_t)mt*64)*DD;
    {
        const __half* s0 = Qh_ + qoff;
        const __half* s1 = Ql_ + qoff;
#pragma unroll
        for (int i = 0; i < 8; i++) {
            const int idx = tid + i*128;
            const int row = idx >> 4, ch = idx & 15;
            CP_ASYNC16(sQh + row*FA_STRIDE + ch*16, s0 + row*128 + ch*8);
            CP_ASYNC16(sQl + row*FA_STRIDE + ch*16, s1 + row*128 + ch*8);
        }
        CP_COMMIT();
    }

    auto issueKV = [&](int nt, int st) {
        const size_t koff = ((size_t)bh*SS + (size_t)nt*64)*DD;
        const __half* srcs[2] = {K_+koff, V_+koff};
        const uint32_t base = sb + 2*FA_TILE + st*2*FA_TILE;
#pragma unroll
        for (int t2 = 0; t2 < 2; t2++) {
            const uint32_t dt = base + t2*FA_TILE;
            const __half* s = srcs[t2];
#pragma unroll
            for (int i = 0; i < 8; i++) {
                const int idx = tid + i*128;
                const int row = idx >> 4, ch = idx & 15;
                CP_ASYNC16(dt + row*FA_STRIDE + ch*16, s + row*128 + ch*8);
            }
        }
        CP_COMMIT();
    };

    float o[16][4];
#pragma unroll
    for (int j = 0; j < 16; j++)
#pragma unroll
        for (int e = 0; e < 4; e++) o[j][e] = 0.f;
    float mrow0 = -1e30f, mrow1 = -1e30f, se0 = 0.f, se1 = 0.f;

    const uint32_t a_row   = wid*16 + ((grp & 1) << 3) + r8;
    const uint32_t a_par   = (grp >> 1);
    const uint32_t b_row   = ((grp >> 1) << 3) + r8;
    const uint32_t b_par   = (grp & 1);
    const uint32_t v_krow  = ((grp & 1) << 3) + r8;
    const uint32_t v_ncol  = ((grp >> 1) << 3);

    issueKV(0, 0);

    for (int nt = 0; nt <= mt; nt++) {
        const int st = nt & 1;
        __syncthreads();
        if (nt < mt) { issueKV(nt + 1, st ^ 1); CP_WAIT(1); }
        else         { CP_WAIT(0); }
        __syncthreads();

        const uint32_t sK = sb + 2*FA_TILE + st*2*FA_TILE;
        const uint32_t sV = sK + FA_TILE;

        // ---- scores S = Q K^T (Q 2-term x K single) ----
        float s[8][4];
#pragma unroll
        for (int j = 0; j < 8; j++)
#pragma unroll
            for (int e = 0; e < 4; e++) s[j][e] = 0.f;

#pragma unroll
        for (int k = 0; k < 8; k++) {
            uint32_t qfh[4], qfl[4];
            const uint32_t qa = sQh + a_row*FA_STRIDE + k*32 + a_par*16;
            ldm_x4(qa, qfh[0], qfh[1], qfh[2], qfh[3]);
            ldm_x4(qa + FA_TILE, qfl[0], qfl[1], qfl[2], qfl[3]);
#pragma unroll
            for (int p = 0; p < 4; p++) {
                uint32_t kf[2][2];
                const uint32_t ka = sK + (p*16 + b_row)*FA_STRIDE + k*32 + b_par*16;
                ldm_x4(ka, kf[0][0], kf[0][1], kf[1][0], kf[1][1]);
                mma_f16(s[2*p],   qfh, kf[0]);
                mma_f16(s[2*p],   qfl, kf[0]);
                mma_f16(s[2*p+1], qfh, kf[1]);
                mma_f16(s[2*p+1], qfl, kf[1]);
            }
        }

        if (nt == mt) {
            const int gi0 = mt*64 + wid*16 + tq;
            const int gi1 = gi0 + 8;
#pragma unroll
            for (int j = 0; j < 8; j++) {
                const int gj0 = nt*64 + j*8 + tr*2;
                if (gj0     > gi0) s[j][0] = -1e30f;
                if (gj0 + 1 > gi0) s[j][1] = -1e30f;
                if (gj0     > gi1) s[j][2] = -1e30f;
                if (gj0 + 1 > gi1) s[j][3] = -1e30f;
            }
        }

        // ---- online softmax in fragment layout ----
        float mx0 = -1e30f, mx1 = -1e30f;
#pragma unroll
        for (int j = 0; j < 8; j++) {
            mx0 = fmaxf(mx0, fmaxf(s[j][0], s[j][1]));
            mx1 = fmaxf(mx1, fmaxf(s[j][2], s[j][3]));
        }
        mx0 = fmaxf(mx0, __shfl_xor_sync(0xffffffffu, mx0, 1));
        mx0 = fmaxf(mx0, __shfl_xor_sync(0xffffffffu, mx0, 2));
        mx1 = fmaxf(mx1, __shfl_xor_sync(0xffffffffu, mx1, 1));
        mx1 = fmaxf(mx1, __shfl_xor_sync(0xffffffffu, mx1, 2));
        const float nm0 = fmaxf(mrow0, mx0);
        const float nm1 = fmaxf(mrow1, mx1);
        const float c0 = expf(mrow0 - nm0);
        const float c1 = expf(mrow1 - nm1);
        float sum0 = 0.f, sum1 = 0.f;
#pragma unroll
        for (int j = 0; j < 8; j++) {
            s[j][0] = expf(s[j][0] - nm0); sum0 += s[j][0];
            s[j][1] = expf(s[j][1] - nm0); sum0 += s[j][1];
            s[j][2] = expf(s[j][2] - nm1); sum1 += s[j][2];
            s[j][3] = expf(s[j][3] - nm1); sum1 += s[j][3];
        }
        sum0 += __shfl_xor_sync(0xffffffffu, sum0, 1);
        sum0 += __shfl_xor_sync(0xffffffffu, sum0, 2);
        sum1 += __shfl_xor_sync(0xffffffffu, sum1, 1);
        sum1 += __shfl_xor_sync(0xffffffffu, sum1, 2);
        se0 = se0 * c0 + sum0;
        se1 = se1 * c1 + sum1;
        mrow0 = nm0; mrow1 = nm1;
#pragma unroll
        for (int j = 0; j < 16; j++) {
            o[j][0] *= c0; o[j][1] *= c0;
            o[j][2] *= c1; o[j][3] *= c1;
        }

        // ---- P -> fp16 single A-fragments (C-frag layout identity) ----
        uint32_t ph[4][4];
#pragma unroll
        for (int t = 0; t < 4; t++) {
#pragma unroll
            for (int hf = 0; hf < 2; hf++) {
                const int tile = 2*t + hf;
                ph[t][2*hf+0] = pack_f16(s[tile][0], s[tile][1]);
                ph[t][2*hf+1] = pack_f16(s[tile][2], s[tile][3]);
            }
        }

        // ---- O += P V (P single x V single), V via ldmatrix.trans ----
#pragma unroll
        for (int t = 0; t < 4; t++) {
#pragma unroll
            for (int p = 0; p < 8; p++) {
                uint32_t vf[2][2];
                const uint32_t va = sV + (t*16 + v_krow)*FA_STRIDE
                                  + (p*16 + v_ncol)*2;
                ldm_x4t(va, vf[0][0], vf[0][1], vf[1][0], vf[1][1]);
                mma_f16(o[2*p],   ph[t], vf[0]);
                mma_f16(o[2*p+1], ph[t], vf[1]);
            }
        }
    }

    // ---- epilogue: write fp16 hi/lo for o-proj GEMM ----
    const float i0 = 1.f / (se0 + 1e-5f);
    const float i1 = 1.f / (se1 + 1e-5f);
    const int s0 = mt*64 + wid*16 + tq;
    const size_t off0 = ((size_t)(b*SS + s0))*(HH*DD) + h*DD;
    const size_t off1 = off0 + (size_t)8*(HH*DD);
#pragma unroll
    for (int j = 0; j < 16; j++) {
        const int col = j*8 + tr*2;
        const float v0 = o[j][0]*i0, v1 = o[j][1]*i0;
        const float v2 = o[j][2]*i1, v3 = o[j][3]*i1;
        const __half h0 = __float2half(v0), h1 = __float2half(v1);
        const __half h2 = __float2half(v2), h3 = __float2half(v3);
        *(__half2*)(Oh + off0 + col) = __halves2half2(h0, h1);
        *(__half2*)(Oh + off1 + col) = __halves2half2(h2, h3);
        *(__half2*)(Ol + off0 + col) =
            __halves2half2(__float2half(v0 - __half2float(h0)),
                           __float2half(v1 - __half2float(h1)));
        *(__half2*)(Ol + off1 + col) =
            __halves2half2(__float2half(v2 - __half2float(h2)),
                           __float2half(v3 - __half2float(h3)));
    }
}

// ---------------- launch --------------------------------------------------------
extern "C" void kernel_launch(void* const* d_in, const int* in_sizes, int n_in,
                              void* d_out, int out_size)
{
    const float* hidden = (const float*)d_in[0];
    const int*   pos    = (const int*)  d_in[1];
    const float* w_q    = (const float*)d_in[2];
    const float* w_kv_a = (const float*)d_in[3];
    const float* w_kv_b = (const float*)d_in[4];
    const float* w_o    = (const float*)d_in[5];
    const float* kv_ln  = (const float*)d_in[6];
    float* out = (float*)d_out;

    float *q, *kva, *kvb;
    cudaGetSymbolAddress((void**)&q,    g_q);
    cudaGetSymbolAddress((void**)&kva,  g_kva);
    cudaGetSymbolAddress((void**)&kvb,  g_kvb);

    __half *fqh, *fql, *fk, *fv;
    cudaGetSymbolAddress((void**)&fqh, g_fqh);
    cudaGetSymbolAddress((void**)&fql, g_fql);
    cudaGetSymbolAddress((void**)&fk,  g_fk);
    cudaGetSymbolAddress((void**)&fv,  g_fv);

    __half *ah, *al, *ckvh, *ckvl, *bq, *bka, *bkb, *bo;
    cudaGetSymbolAddress((void**)&ah,   g_ah);
    cudaGetSymbolAddress((void**)&al,   g_al);
    cudaGetSymbolAddress((void**)&ckvh, g_ckvh);
    cudaGetSymbolAddress((void**)&ckvl, g_ckvl);
    cudaGetSymbolAddress((void**)&bq,   g_bq);
    cudaGetSymbolAddress((void**)&bka,  g_bka);
    cudaGetSymbolAddress((void**)&bkb,  g_bkb);
    cudaGetSymbolAddress((void**)&bo,   g_bo);

    cudaFuncSetAttribute(hgemm, cudaFuncAttributeMaxDynamicSharedMemorySize, HG_SMEM);
    cudaFuncSetAttribute(flash_mma, cudaFuncAttributeMaxDynamicSharedMemorySize, FA_SMEM);

    // weight conversions (transpose, fp16 single):  X[K,N] -> Bt[N,K]
    split_T1<<<dim3(HH*DD/32, HID/32),   256>>>(w_q,    bq,  HID,  HH*DD);
    split_T1<<<dim3(KVA_N/32, HID/32),   256>>>(w_kv_a, bka, HID,  KVA_N);
    split_T1<<<dim3(HH*2*DD/32, RANK/32),256>>>(w_kv_b, bkb, RANK, HH*2*DD);
    split_T1<<<dim3(HID/32, HH*DD/32),   256>>>(w_o,    bo,  HH*DD, HID);
    // hidden split (fp16 hi/lo)
    split_rows_h<<<(BS*HID/4 + 255)/256, 256>>>(hidden, ah, al, BS*HID/4);

    // 1. q = hidden @ w_q
    hgemm<<<dim3((HH*DD)/128, BS/128), 256, HG_SMEM>>>(ah, al, bq, q, BS, HH*DD, HID);
    // 2. kv_a = hidden @ w_kv_a
    hgemm<<<dim3(KVA_N/128, BS/128), 256, HG_SMEM>>>(ah, al, bka, kva, BS, KVA_N, HID);
    // 3. RMSNorm (fused fp16 split)
    rmsnorm_k<<<BS, 256>>>(kva, kv_ln, ckvh, ckvl);
    // 4. kv = c_kv @ w_kv_b
    hgemm<<<dim3((HH*2*DD)/128, BS/128), 256, HG_SMEM>>>(ckvh, ckvl, bkb, kvb,
                                                         BS, HH*2*DD, RANK);
    // 5. RoPE + assemble (fp16: q hi/lo pre-scaled, k/v single)
    rope_combine<<<BS, 256>>>(q, kva, kvb, pos, fqh, fql, fk, fv);
    // 6. tensor-core flash attention (writes fp16 hi/lo into ah/al)
    flash_mma<<<dim3(SS/64, BB*HH), 128, FA_SMEM>>>(fqh, fql, fk, fv, ah, al);
    // 7. out = attn @ w_o
    hgemm<<<dim3(HID/128, BS/128), 256, HG_SMEM>>>(ah, al, bo, out, BS, HID, HH*DD);
}